// round 6
// baseline (speedup 1.0000x reference)
#include <cuda_runtime.h>
#include <cuda_bf16.h>
#include <cstdint>

#define N_NODES   50000
#define IN_FEAT   64
#define HIDDEN    128
#define N_EDGES   800000
#define NUM_LAYERS 3
#define NBLK      ((N_NODES + 255) / 256)   // 196

// ---------------- scratch (device globals; no allocation allowed) ------------
__device__ __align__(128) float g_hA [N_NODES * HIDDEN];
__device__ __align__(128) float g_hB [N_NODES * HIDDEN];
__device__ __align__(128) float g_gh [N_NODES * HIDDEN];
__device__ int g_cnt   [N_NODES];
__device__ int g_offs  [N_NODES + 1];
__device__ int g_cursor[N_NODES];
__device__ int g_esrc  [N_EDGES];
__device__ int g_bsum  [NBLK];
__device__ int g_is64;
// fragment-major bf16 hi/lo weights: slot0 = W_in (4096 w), layer l at 4096 + l*16384
__device__ __align__(256) uint32_t g_whi[4096 + 3 * 16384];
__device__ __align__(256) uint32_t g_wlo[4096 + 3 * 16384];

// ---------------- bf16 split helpers -----------------------------------------
__device__ __forceinline__ uint32_t pack_bf16x2(float x, float y) {
    uint32_t r;
    asm("cvt.rn.bf16x2.f32 %0, %1, %2;" : "=r"(r) : "f"(y), "f"(x));
    return r;
}
__device__ __forceinline__ void split2(float2 v, uint32_t& hi, uint32_t& lo) {
    hi = pack_bf16x2(v.x, v.y);
    float hx = __uint_as_float(hi << 16);
    float hy = __uint_as_float(hi & 0xFFFF0000u);
    lo = pack_bf16x2(v.x - hx, v.y - hy);
}
__device__ __forceinline__ void mma_bf16(float* c, const uint32_t* a, uint32_t b0, uint32_t b1) {
    asm volatile(
        "mma.sync.aligned.m16n8k16.row.col.f32.bf16.bf16.f32 "
        "{%0,%1,%2,%3}, {%4,%5,%6,%7}, {%8,%9}, {%0,%1,%2,%3};"
        : "+f"(c[0]), "+f"(c[1]), "+f"(c[2]), "+f"(c[3])
        : "r"(a[0]), "r"(a[1]), "r"(a[2]), "r"(a[3]), "r"(b0), "r"(b1));
}

// ---------------- index helpers ----------------------------------------------
__device__ __forceinline__ int load_src(const int* ei, int e, int is64) {
    return is64 ? ei[2 * e] : ei[e];
}
__device__ __forceinline__ int load_dst(const int* ei, int e, int is64) {
    return is64 ? ei[2 * (N_EDGES + e)] : ei[N_EDGES + e];
}

// ---------------- dtype detect -------------------------------------------------
__global__ void detect_k(const int* __restrict__ ei) {
    int lane = threadIdx.x;
    int bad = 0;
    for (int i = lane; i < 256; i += 32) bad |= (ei[2 * i + 1] != 0);
    bad = __any_sync(0xFFFFFFFFu, bad);
    if (lane == 0) g_is64 = !bad;
}

// ---------------- zero / count --------------------------------------------------
__global__ void zero_int_k(int* __restrict__ p, int n) {
    int i = blockIdx.x * blockDim.x + threadIdx.x;
    if (i < n) p[i] = 0;
}
__global__ void count_k(const int* __restrict__ ei) {
    int e = blockIdx.x * blockDim.x + threadIdx.x;
    if (e >= N_EDGES) return;
    atomicAdd(&g_cnt[load_dst(ei, e, g_is64)], 1);
}

// ---------------- 3-phase scan ----------------------------------------------------
__global__ __launch_bounds__(256) void scan1_k() {
    __shared__ int ws[8];
    int idx = blockIdx.x * 256 + threadIdx.x;
    int v = (idx < N_NODES) ? g_cnt[idx] : 0;
    int lane = threadIdx.x & 31, wid = threadIdx.x >> 5;
    for (int d = 16; d > 0; d >>= 1) v += __shfl_down_sync(0xFFFFFFFFu, v, d);
    if (lane == 0) ws[wid] = v;
    __syncthreads();
    if (threadIdx.x == 0) {
        int s = 0;
        for (int i = 0; i < 8; i++) s += ws[i];
        g_bsum[blockIdx.x] = s;
    }
}
__global__ __launch_bounds__(256) void scan2_k() {
    __shared__ int sh[256];
    int t = threadIdx.x;
    int v = (t < NBLK) ? g_bsum[t] : 0;
    sh[t] = v;
    __syncthreads();
    for (int d = 1; d < 256; d <<= 1) {
        int n = (t >= d) ? sh[t - d] : 0;
        __syncthreads();
        sh[t] += n;
        __syncthreads();
    }
    if (t < NBLK) g_bsum[t] = sh[t] - v;   // exclusive prefix
}
__global__ __launch_bounds__(256) void scan3_k() {
    __shared__ int sh[256];
    int t = threadIdx.x;
    int idx = blockIdx.x * 256 + t;
    int v = (idx < N_NODES) ? g_cnt[idx] : 0;
    sh[t] = v;
    __syncthreads();
    for (int d = 1; d < 256; d <<= 1) {
        int n = (t >= d) ? sh[t - d] : 0;
        __syncthreads();
        sh[t] += n;
        __syncthreads();
    }
    int ex = g_bsum[blockIdx.x] + sh[t] - v;
    if (idx < N_NODES) {
        g_offs[idx]   = ex;
        g_cursor[idx] = ex;
        if (idx == N_NODES - 1) g_offs[N_NODES] = ex + v;
    }
}

// ---------------- CSR fill --------------------------------------------------------
__global__ void fill_k(const int* __restrict__ ei) {
    int e = blockIdx.x * blockDim.x + threadIdx.x;
    if (e >= N_EDGES) return;
    int is64 = g_is64;
    int s = load_src(ei, e, is64);
    int d = load_dst(ei, e, is64);
    g_esrc[atomicAdd(&g_cursor[d], 1)] = s;
}

// ---------------- weight convert ---------------------------------------------------
// fragment-major word index: ((J * NSTEP + s) * 32 + lane) * 2 + r
//   k = s*16 + (lane&3)*2 + r*8, n = J*8 + (lane>>2)
// input projection: K_=64, source W_in [64,128]
__global__ void conv_w_k(const float* __restrict__ W) {
    uint32_t* hi = g_whi;
    uint32_t* lo = g_wlo;
    constexpr int NSTEP = 4;
    int total = 16 * NSTEP * 64;
    for (int idx = blockIdx.x * blockDim.x + threadIdx.x; idx < total;
         idx += gridDim.x * blockDim.x) {
        int J = idx / (NSTEP * 64);
        int rem = idx % (NSTEP * 64);
        int s = rem / 64;
        int rem2 = rem % 64;
        int l = rem2 >> 1, r = rem2 & 1;
        int k = s * 16 + (l & 3) * 2 + r * 8;
        int n = J * 8 + (l >> 2);
        float v0 = W[(size_t)k * HIDDEN + n];
        float v1 = W[(size_t)(k + 1) * HIDDEN + n];
        uint32_t h, lw;
        split2(make_float2(v0, v1), h, lw);
        hi[idx] = h;
        lo[idx] = lw;
    }
}
// concatenated layer weights: K_=256, rows 0-127 from Ws, 128-255 from Wn
__global__ void conv_cat_k(const float* __restrict__ Ws,
                           const float* __restrict__ Wn, int layer) {
    uint32_t* hi = g_whi + 4096 + layer * 16384;
    uint32_t* lo = g_wlo + 4096 + layer * 16384;
    constexpr int NSTEP = 16;
    int total = 16 * NSTEP * 64;   // 16384
    for (int idx = blockIdx.x * blockDim.x + threadIdx.x; idx < total;
         idx += gridDim.x * blockDim.x) {
        int J = idx / (NSTEP * 64);
        int rem = idx % (NSTEP * 64);
        int s = rem / 64;
        int rem2 = rem % 64;
        int l = rem2 >> 1, r = rem2 & 1;
        int k = s * 16 + (l & 3) * 2 + r * 8;
        int n = J * 8 + (l >> 2);
        const float* W0 = (k < 128) ? Ws : Wn;
        int kk = k & 127;
        float v0 = W0[(size_t)kk * HIDDEN + n];
        float v1 = W0[(size_t)(kk + 1) * HIDDEN + n];
        uint32_t h, lw;
        split2(make_float2(v0, v1), h, lw);
        hi[idx] = h;
        lo[idx] = lw;
    }
}

// ---------------- mma.sync GEMM ---------------------------------------------------
// C[M x 128] = [A0 | A1] @ W  (K_ = 128 per A source when A1 != null, else K_ total)
// bf16-split 3-pass, fp32 accumulate. 8 warps (4m x 2n), warp tile 32x64.
// MODE 1: C = A0@W + bias            (K_ = IN_FEAT, A1 unused)
// MODE 2: C = elu([A0|A1]@W + bias)  (K_ = 256 concat)
template <int K_, int MODE>
__global__ __launch_bounds__(256, 2)
void gemm_mma_k(const float* __restrict__ A0, const float* __restrict__ A1,
                const uint32_t* __restrict__ Bhi, const uint32_t* __restrict__ Blo,
                const float* __restrict__ bias,
                float* __restrict__ C, int M) {
    constexpr int NSTEP = K_ / 16;
    const int tid  = threadIdx.x;
    const int warp = tid >> 5;
    const int lane = tid & 31;
    const int g = lane >> 2, t = lane & 3;
    const int warp_m = (warp & 3) * 32;
    const int warp_n = (warp >> 2) * 64;
    const int row_base = blockIdx.x * 128 + warp_m;

    float acc[2][8][4];
#pragma unroll
    for (int mt = 0; mt < 2; mt++)
#pragma unroll
        for (int j = 0; j < 8; j++)
#pragma unroll
            for (int q = 0; q < 4; q++) acc[mt][j][q] = 0.f;

#pragma unroll
    for (int s = 0; s < NSTEP; s++) {
        const float* A = (MODE == 2 && s >= NSTEP / 2) ? A1 : A0;
        const int ks   = (MODE == 2 && s >= NSTEP / 2) ? s - NSTEP / 2 : s;
        constexpr int LDA = (MODE == 2) ? HIDDEN : K_;
        uint32_t ahi[2][4], alo[2][4];
        const int c0 = ks * 16 + t * 2;
#pragma unroll
        for (int mt = 0; mt < 2; mt++) {
            int r0 = row_base + mt * 16 + g;
            int r1 = r0 + 8;
            float2 v00 = make_float2(0.f, 0.f), v10 = v00, v01 = v00, v11 = v00;
            if (r0 < M) {
                v00 = *(const float2*)(A + (size_t)r0 * LDA + c0);
                v01 = *(const float2*)(A + (size_t)r0 * LDA + c0 + 8);
            }
            if (r1 < M) {
                v10 = *(const float2*)(A + (size_t)r1 * LDA + c0);
                v11 = *(const float2*)(A + (size_t)r1 * LDA + c0 + 8);
            }
            split2(v00, ahi[mt][0], alo[mt][0]);
            split2(v10, ahi[mt][1], alo[mt][1]);
            split2(v01, ahi[mt][2], alo[mt][2]);
            split2(v11, ahi[mt][3], alo[mt][3]);
        }
#pragma unroll
        for (int j = 0; j < 8; j++) {
            int J = (warp >> 2) * 8 + j;
            int w = ((J * NSTEP + s) * 32 + lane) * 2;
            uint32_t b0h = Bhi[w], b1h = Bhi[w + 1];
            uint32_t b0l = Blo[w], b1l = Blo[w + 1];
#pragma unroll
            for (int mt = 0; mt < 2; mt++) {
                mma_bf16(acc[mt][j], ahi[mt], b0h, b1h);
                mma_bf16(acc[mt][j], ahi[mt], b0l, b1l);
                mma_bf16(acc[mt][j], alo[mt], b0h, b1h);
            }
        }
    }

    // epilogue
#pragma unroll
    for (int j = 0; j < 8; j++) {
        int n0 = warp_n + j * 8 + t * 2;
        float2 bv = *(const float2*)(bias + n0);
#pragma unroll
        for (int mt = 0; mt < 2; mt++) {
            int r0 = row_base + mt * 16 + g;
            int r1 = r0 + 8;
            float vx0 = acc[mt][j][0] + bv.x, vy0 = acc[mt][j][1] + bv.y;
            float vx1 = acc[mt][j][2] + bv.x, vy1 = acc[mt][j][3] + bv.y;
            if (MODE == 2) {
                vx0 = (vx0 > 0.f) ? vx0 : expm1f(vx0);
                vy0 = (vy0 > 0.f) ? vy0 : expm1f(vy0);
                vx1 = (vx1 > 0.f) ? vx1 : expm1f(vx1);
                vy1 = (vy1 > 0.f) ? vy1 : expm1f(vy1);
            }
            if (r0 < M) *(float2*)(C + (size_t)r0 * HIDDEN + n0) = make_float2(vx0, vy0);
            if (r1 < M) *(float2*)(C + (size_t)r1 * HIDDEN + n0) = make_float2(vx1, vy1);
        }
    }
}

// ---------------- gather: gh[n] = (sum_{e in CSR[n]} h[src_e]) / max(deg,1) ----------
__global__ __launch_bounds__(256)
void gather_k(const float* __restrict__ h, float* __restrict__ gh) {
    int gtid = blockIdx.x * blockDim.x + threadIdx.x;
    int node = gtid >> 5;
    if (node >= N_NODES) return;
    int lane = gtid & 31;
    int c = lane * 4;

    int start = g_offs[node];
    int end   = g_offs[node + 1];

    float4 acc = make_float4(0.f, 0.f, 0.f, 0.f);
    int e = start;
    for (; e + 4 <= end; e += 4) {
        int s0 = g_esrc[e + 0], s1 = g_esrc[e + 1], s2 = g_esrc[e + 2], s3 = g_esrc[e + 3];
        float4 v0 = __ldg((const float4*)(h + (size_t)s0 * HIDDEN + c));
        float4 v1 = __ldg((const float4*)(h + (size_t)s1 * HIDDEN + c));
        float4 v2 = __ldg((const float4*)(h + (size_t)s2 * HIDDEN + c));
        float4 v3 = __ldg((const float4*)(h + (size_t)s3 * HIDDEN + c));
        acc.x += v0.x + v1.x + v2.x + v3.x;
        acc.y += v0.y + v1.y + v2.y + v3.y;
        acc.z += v0.z + v1.z + v2.z + v3.z;
        acc.w += v0.w + v1.w + v2.w + v3.w;
    }
    for (; e < end; e++) {
        int s = g_esrc[e];
        float4 v = __ldg((const float4*)(h + (size_t)s * HIDDEN + c));
        acc.x += v.x; acc.y += v.y; acc.z += v.z; acc.w += v.w;
    }

    float inv = 1.0f / fmaxf((float)(end - start), 1.0f);
    *(float4*)(gh + (size_t)node * HIDDEN + c) =
        make_float4(acc.x * inv, acc.y * inv, acc.z * inv, acc.w * inv);
}

// ---------------- launch ----------------------------------------------------------
extern "C" void kernel_launch(void* const* d_in, const int* in_sizes, int n_in,
                              void* d_out, int out_size) {
    const float* x      = (const float*)d_in[0];
    const int*   ei     = (const int*)d_in[1];
    const float* W_in   = (const float*)d_in[2];
    const float* b_in   = (const float*)d_in[3];
    const float* W_self = (const float*)d_in[4];
    const float* b_self = (const float*)d_in[5];
    const float* W_nbr  = (const float*)d_in[6];
    float*       out    = (float*)d_out;

    float* hA; cudaGetSymbolAddress((void**)&hA, g_hA);
    float* hB; cudaGetSymbolAddress((void**)&hB, g_hB);
    float* gh; cudaGetSymbolAddress((void**)&gh, g_gh);
    int*   cnt; cudaGetSymbolAddress((void**)&cnt, g_cnt);
    uint32_t* whi; cudaGetSymbolAddress((void**)&whi, g_whi);
    uint32_t* wlo; cudaGetSymbolAddress((void**)&wlo, g_wlo);

    const int M = N_NODES;
    const int gemm_blocks = (M + 127) / 128;   // 391

    // ---- CSR build ----
    detect_k<<<1, 32>>>(ei);
    zero_int_k<<<(N_NODES + 255) / 256, 256>>>(cnt, N_NODES);
    count_k<<<(N_EDGES + 255) / 256, 256>>>(ei);
    scan1_k<<<NBLK, 256>>>();
    scan2_k<<<1, 256>>>();
    scan3_k<<<NBLK, 256>>>();
    fill_k<<<(N_EDGES + 255) / 256, 256>>>(ei);

    // ---- weight packing: W_in + per-layer concat [Ws ; Wn] ----
    conv_w_k<<<16, 256>>>(W_in);
    for (int l = 0; l < NUM_LAYERS; l++)
        conv_cat_k<<<32, 256>>>(W_self + (size_t)l * HIDDEN * HIDDEN,
                                W_nbr  + (size_t)l * HIDDEN * HIDDEN, l);

    // ---- input projection: hA = x @ W_in + b_in ----
    gemm_mma_k<IN_FEAT, 1><<<gemm_blocks, 256>>>(x, nullptr, whi, wlo, b_in, hA, M);

    const float* hcur = hA;
    for (int l = 0; l < NUM_LAYERS; l++) {
        const float* bs = b_self + (size_t)l * HIDDEN;
        float* hnext = (l == NUM_LAYERS - 1) ? out : ((hcur == hA) ? hB : hA);
        const uint32_t* bhi = whi + 4096 + l * 16384;
        const uint32_t* blo = wlo + 4096 + l * 16384;

        // gh = gather(h)/deg
        gather_k<<<(N_NODES * 32 + 255) / 256, 256>>>(hcur, gh);
        // hnext = elu([h | gh] @ [Ws;Wn] + b)
        gemm_mma_k<256, 2><<<gemm_blocks, 256>>>(hcur, gh, bhi, blo, bs, hnext, M);

        hcur = hnext;
    }
}

// round 7
// speedup vs baseline: 1.1038x; 1.1038x over previous
#include <cuda_runtime.h>
#include <cuda_bf16.h>
#include <cstdint>

#define N_NODES   50000
#define IN_FEAT   64
#define HIDDEN    128
#define N_EDGES   800000
#define NUM_LAYERS 3
#define NBLK      ((N_NODES + 255) / 256)   // 196
#define HPAIRS    (HIDDEN / 2)              // 64 uint2 per row

// ---------------- scratch (device globals; no allocation allowed) ------------
__device__ __align__(128) uint2 g_hpkA[N_NODES * HPAIRS];  // packed h (hi,lo bf16x2)
__device__ __align__(128) uint2 g_hpkB[N_NODES * HPAIRS];
__device__ __align__(128) float g_t  [N_NODES * HIDDEN];
__device__ __align__(128) float g_z  [N_NODES * HIDDEN];
__device__ int g_cnt   [N_NODES];
__device__ int g_offs  [N_NODES + 1];
__device__ int g_cursor[N_NODES];
__device__ int g_esrc  [N_EDGES];
__device__ int g_bsum  [NBLK];
__device__ int g_is64;
// interleaved fragment-major weights: uint4 {b0h,b1h,b0l,b1l}
// W_in: 2048 uint4 at 0; Wn[l]: 2048 + l*4096; Ws[l]: 2048 + (3+l)*4096
__device__ __align__(256) uint4 g_w4[2048 + 6 * 4096];

// ---------------- bf16 split helpers -----------------------------------------
__device__ __forceinline__ uint32_t pack_bf16x2(float x, float y) {
    uint32_t r;
    asm("cvt.rn.bf16x2.f32 %0, %1, %2;" : "=r"(r) : "f"(y), "f"(x));
    return r;
}
__device__ __forceinline__ void split2(float2 v, uint32_t& hi, uint32_t& lo) {
    hi = pack_bf16x2(v.x, v.y);
    float hx = __uint_as_float(hi << 16);
    float hy = __uint_as_float(hi & 0xFFFF0000u);
    lo = pack_bf16x2(v.x - hx, v.y - hy);
}
__device__ __forceinline__ void mma_bf16(float* c, const uint32_t* a, uint32_t b0, uint32_t b1) {
    asm volatile(
        "mma.sync.aligned.m16n8k16.row.col.f32.bf16.bf16.f32 "
        "{%0,%1,%2,%3}, {%4,%5,%6,%7}, {%8,%9}, {%0,%1,%2,%3};"
        : "+f"(c[0]), "+f"(c[1]), "+f"(c[2]), "+f"(c[3])
        : "r"(a[0]), "r"(a[1]), "r"(a[2]), "r"(a[3]), "r"(b0), "r"(b1));
}

// ---------------- index helpers ----------------------------------------------
__device__ __forceinline__ int load_src(const int* ei, int e, int is64) {
    return is64 ? ei[2 * e] : ei[e];
}
__device__ __forceinline__ int load_dst(const int* ei, int e, int is64) {
    return is64 ? ei[2 * (N_EDGES + e)] : ei[N_EDGES + e];
}

// ---------------- dtype detect -------------------------------------------------
__global__ void detect_k(const int* __restrict__ ei) {
    int lane = threadIdx.x;
    int bad = 0;
    for (int i = lane; i < 256; i += 32) bad |= (ei[2 * i + 1] != 0);
    bad = __any_sync(0xFFFFFFFFu, bad);
    if (lane == 0) g_is64 = !bad;
}

// ---------------- zero / count --------------------------------------------------
__global__ void zero_int_k(int* __restrict__ p, int n) {
    int i = blockIdx.x * blockDim.x + threadIdx.x;
    if (i < n) p[i] = 0;
}
__global__ void count_k(const int* __restrict__ ei) {
    int e = blockIdx.x * blockDim.x + threadIdx.x;
    if (e >= N_EDGES) return;
    atomicAdd(&g_cnt[load_dst(ei, e, g_is64)], 1);
}

// ---------------- 3-phase scan ----------------------------------------------------
__global__ __launch_bounds__(256) void scan1_k() {
    __shared__ int ws[8];
    int idx = blockIdx.x * 256 + threadIdx.x;
    int v = (idx < N_NODES) ? g_cnt[idx] : 0;
    int lane = threadIdx.x & 31, wid = threadIdx.x >> 5;
    for (int d = 16; d > 0; d >>= 1) v += __shfl_down_sync(0xFFFFFFFFu, v, d);
    if (lane == 0) ws[wid] = v;
    __syncthreads();
    if (threadIdx.x == 0) {
        int s = 0;
        for (int i = 0; i < 8; i++) s += ws[i];
        g_bsum[blockIdx.x] = s;
    }
}
__global__ __launch_bounds__(256) void scan2_k() {
    __shared__ int sh[256];
    int t = threadIdx.x;
    int v = (t < NBLK) ? g_bsum[t] : 0;
    sh[t] = v;
    __syncthreads();
    for (int d = 1; d < 256; d <<= 1) {
        int n = (t >= d) ? sh[t - d] : 0;
        __syncthreads();
        sh[t] += n;
        __syncthreads();
    }
    if (t < NBLK) g_bsum[t] = sh[t] - v;   // exclusive prefix
}
__global__ __launch_bounds__(256) void scan3_k() {
    __shared__ int sh[256];
    int t = threadIdx.x;
    int idx = blockIdx.x * 256 + t;
    int v = (idx < N_NODES) ? g_cnt[idx] : 0;
    sh[t] = v;
    __syncthreads();
    for (int d = 1; d < 256; d <<= 1) {
        int n = (t >= d) ? sh[t - d] : 0;
        __syncthreads();
        sh[t] += n;
        __syncthreads();
    }
    int ex = g_bsum[blockIdx.x] + sh[t] - v;
    if (idx < N_NODES) {
        g_offs[idx]   = ex;
        g_cursor[idx] = ex;
        if (idx == N_NODES - 1) g_offs[N_NODES] = ex + v;
    }
}

// ---------------- CSR fill --------------------------------------------------------
__global__ void fill_k(const int* __restrict__ ei) {
    int e = blockIdx.x * blockDim.x + threadIdx.x;
    if (e >= N_EDGES) return;
    int is64 = g_is64;
    int s = load_src(ei, e, is64);
    int d = load_dst(ei, e, is64);
    g_esrc[atomicAdd(&g_cursor[d], 1)] = s;
}

// ---------------- weight convert: W[K_,128] -> interleaved fragment uint4 ----------
// one uint4 per (J, s, lane): {b0h, b1h, b0l, b1l}
//   t=lane&3, g=lane>>2; k0 = s*16 + t*2 (pair k0,k0+1), k1 = k0+8; n = J*8+g
__global__ void conv_w_k(const float* __restrict__ W, int K_, uint4* __restrict__ dst) {
    int NSTEP = K_ / 16;
    int total = 16 * NSTEP * 32;
    for (int idx = blockIdx.x * blockDim.x + threadIdx.x; idx < total;
         idx += gridDim.x * blockDim.x) {
        int lane = idx & 31;
        int s = (idx >> 5) % NSTEP;
        int J = idx / (NSTEP * 32);
        int t = lane & 3, g = lane >> 2;
        int k0 = s * 16 + t * 2;
        int k1 = k0 + 8;
        int n = J * 8 + g;
        uint32_t b0h, b0l, b1h, b1l;
        split2(make_float2(W[(size_t)k0 * HIDDEN + n], W[(size_t)(k0 + 1) * HIDDEN + n]), b0h, b0l);
        split2(make_float2(W[(size_t)k1 * HIDDEN + n], W[(size_t)(k1 + 1) * HIDDEN + n]), b1h, b1l);
        dst[idx] = make_uint4(b0h, b1h, b0l, b1l);
    }
}

// ---------------- mma.sync GEMM ---------------------------------------------------
// C[M x 128] = A[M x K_] @ W. bf16-split 3-pass, fp32 accumulate.
// 8 warps (4m x 2n), warp tile 32x64.
// APACK=1: A is packed uint2 (hi,lo) pairs, 64/row. APACK=0: A fp32, split on the fly.
// OUTMODE 0: fp32   1: fp32+bias   2: packed+bias
template <int K_, int APACK, int OUTMODE>
__global__ __launch_bounds__(256, 2)
void gemm_mma_k(const void* __restrict__ Av,
                const uint4* __restrict__ B4,
                const float* __restrict__ bias,
                void* __restrict__ Cv, int M) {
    constexpr int NSTEP = K_ / 16;
    const int tid  = threadIdx.x;
    const int warp = tid >> 5;
    const int lane = tid & 31;
    const int g = lane >> 2, t = lane & 3;
    const int warp_m = (warp & 3) * 32;
    const int warp_n = (warp >> 2) * 64;
    const int row_base = blockIdx.x * 128 + warp_m;

    float acc[2][8][4];
#pragma unroll
    for (int mt = 0; mt < 2; mt++)
#pragma unroll
        for (int j = 0; j < 8; j++)
#pragma unroll
            for (int q = 0; q < 4; q++) acc[mt][j][q] = 0.f;

#pragma unroll
    for (int s = 0; s < NSTEP; s++) {
        uint32_t ahi[2][4], alo[2][4];
        if (APACK) {
            const uint2* Apk = (const uint2*)Av;
            const int pr = s * 8 + t;
#pragma unroll
            for (int mt = 0; mt < 2; mt++) {
                int r0 = row_base + mt * 16 + g;
                int r1 = r0 + 8;
                uint2 zz = make_uint2(0u, 0u);
                uint2 p00 = zz, p01 = zz, p10 = zz, p11 = zz;
                if (r0 < M) {
                    p00 = Apk[(size_t)r0 * HPAIRS + pr];
                    p01 = Apk[(size_t)r0 * HPAIRS + pr + 4];
                }
                if (r1 < M) {
                    p10 = Apk[(size_t)r1 * HPAIRS + pr];
                    p11 = Apk[(size_t)r1 * HPAIRS + pr + 4];
                }
                ahi[mt][0] = p00.x; alo[mt][0] = p00.y;
                ahi[mt][1] = p10.x; alo[mt][1] = p10.y;
                ahi[mt][2] = p01.x; alo[mt][2] = p01.y;
                ahi[mt][3] = p11.x; alo[mt][3] = p11.y;
            }
        } else {
            const float* A = (const float*)Av;
            const int c0 = s * 16 + t * 2;
#pragma unroll
            for (int mt = 0; mt < 2; mt++) {
                int r0 = row_base + mt * 16 + g;
                int r1 = r0 + 8;
                float2 v00 = make_float2(0.f, 0.f), v10 = v00, v01 = v00, v11 = v00;
                if (r0 < M) {
                    v00 = *(const float2*)(A + (size_t)r0 * K_ + c0);
                    v01 = *(const float2*)(A + (size_t)r0 * K_ + c0 + 8);
                }
                if (r1 < M) {
                    v10 = *(const float2*)(A + (size_t)r1 * K_ + c0);
                    v11 = *(const float2*)(A + (size_t)r1 * K_ + c0 + 8);
                }
                split2(v00, ahi[mt][0], alo[mt][0]);
                split2(v10, ahi[mt][1], alo[mt][1]);
                split2(v01, ahi[mt][2], alo[mt][2]);
                split2(v11, ahi[mt][3], alo[mt][3]);
            }
        }
#pragma unroll
        for (int j = 0; j < 8; j++) {
            int J = (warp >> 2) * 8 + j;
            uint4 b = B4[(size_t)(J * NSTEP + s) * 32 + lane];
#pragma unroll
            for (int mt = 0; mt < 2; mt++) {
                mma_bf16(acc[mt][j], ahi[mt], b.x, b.y);   // hi*Bhi
                mma_bf16(acc[mt][j], ahi[mt], b.z, b.w);   // hi*Blo
                mma_bf16(acc[mt][j], alo[mt], b.x, b.y);   // lo*Bhi
            }
        }
    }

    // epilogue
#pragma unroll
    for (int j = 0; j < 8; j++) {
        int n0 = warp_n + j * 8 + t * 2;
        float2 bv = make_float2(0.f, 0.f);
        if (OUTMODE >= 1) bv = *(const float2*)(bias + n0);
#pragma unroll
        for (int mt = 0; mt < 2; mt++) {
            int r0 = row_base + mt * 16 + g;
            int r1 = r0 + 8;
            float vx0 = acc[mt][j][0] + bv.x, vy0 = acc[mt][j][1] + bv.y;
            float vx1 = acc[mt][j][2] + bv.x, vy1 = acc[mt][j][3] + bv.y;
            if (OUTMODE == 2) {
                uint2* Cpk = (uint2*)Cv;
                uint32_t h0, l0, h1, l1;
                split2(make_float2(vx0, vy0), h0, l0);
                split2(make_float2(vx1, vy1), h1, l1);
                if (r0 < M) Cpk[(size_t)r0 * HPAIRS + (n0 >> 1)] = make_uint2(h0, l0);
                if (r1 < M) Cpk[(size_t)r1 * HPAIRS + (n0 >> 1)] = make_uint2(h1, l1);
            } else {
                float* C = (float*)Cv;
                if (r0 < M) *(float2*)(C + (size_t)r0 * HIDDEN + n0) = make_float2(vx0, vy0);
                if (r1 < M) *(float2*)(C + (size_t)r1 * HIDDEN + n0) = make_float2(vx1, vy1);
            }
        }
    }
}

// ---------------- fused gather + epilogue ------------------------------------------
// r = elu( z[n] + (sum t[src])/max(deg,1) );  LAST: write fp32 out, else packed h
template <int LAST>
__global__ __launch_bounds__(256)
void gather_fused_k(const float* __restrict__ t,
                    const float* __restrict__ z,
                    void* __restrict__ outv) {
    int gtid = blockIdx.x * blockDim.x + threadIdx.x;
    int node = gtid >> 5;
    if (node >= N_NODES) return;
    int lane = gtid & 31;
    int c = lane * 4;

    int start = g_offs[node];
    int end   = g_offs[node + 1];

    float4 acc = make_float4(0.f, 0.f, 0.f, 0.f);
    int e = start;
    for (; e + 4 <= end; e += 4) {
        int s0 = g_esrc[e + 0], s1 = g_esrc[e + 1], s2 = g_esrc[e + 2], s3 = g_esrc[e + 3];
        float4 v0 = __ldg((const float4*)(t + (size_t)s0 * HIDDEN + c));
        float4 v1 = __ldg((const float4*)(t + (size_t)s1 * HIDDEN + c));
        float4 v2 = __ldg((const float4*)(t + (size_t)s2 * HIDDEN + c));
        float4 v3 = __ldg((const float4*)(t + (size_t)s3 * HIDDEN + c));
        acc.x += v0.x + v1.x + v2.x + v3.x;
        acc.y += v0.y + v1.y + v2.y + v3.y;
        acc.z += v0.z + v1.z + v2.z + v3.z;
        acc.w += v0.w + v1.w + v2.w + v3.w;
    }
    for (; e < end; e++) {
        int s = g_esrc[e];
        float4 v = __ldg((const float4*)(t + (size_t)s * HIDDEN + c));
        acc.x += v.x; acc.y += v.y; acc.z += v.z; acc.w += v.w;
    }

    float inv = 1.0f / fmaxf((float)(end - start), 1.0f);
    float4 zv = __ldg((const float4*)(z + (size_t)node * HIDDEN + c));
    float4 r;
    r.x = zv.x + acc.x * inv;
    r.y = zv.y + acc.y * inv;
    r.z = zv.z + acc.z * inv;
    r.w = zv.w + acc.w * inv;
    r.x = (r.x > 0.f) ? r.x : expm1f(r.x);
    r.y = (r.y > 0.f) ? r.y : expm1f(r.y);
    r.z = (r.z > 0.f) ? r.z : expm1f(r.z);
    r.w = (r.w > 0.f) ? r.w : expm1f(r.w);

    if (LAST) {
        *(float4*)((float*)outv + (size_t)node * HIDDEN + c) = r;
    } else {
        uint32_t h0, l0, h1, l1;
        split2(make_float2(r.x, r.y), h0, l0);
        split2(make_float2(r.z, r.w), h1, l1);
        *(uint4*)((uint2*)outv + (size_t)node * HPAIRS + lane * 2) =
            make_uint4(h0, l0, h1, l1);
    }
}

// ---------------- launch ----------------------------------------------------------
extern "C" void kernel_launch(void* const* d_in, const int* in_sizes, int n_in,
                              void* d_out, int out_size) {
    const float* x      = (const float*)d_in[0];
    const int*   ei     = (const int*)d_in[1];
    const float* W_in   = (const float*)d_in[2];
    const float* b_in   = (const float*)d_in[3];
    const float* W_self = (const float*)d_in[4];
    const float* b_self = (const float*)d_in[5];
    const float* W_nbr  = (const float*)d_in[6];
    float*       out    = (float*)d_out;

    uint2* hpkA; cudaGetSymbolAddress((void**)&hpkA, g_hpkA);
    uint2* hpkB; cudaGetSymbolAddress((void**)&hpkB, g_hpkB);
    float* t;    cudaGetSymbolAddress((void**)&t,    g_t);
    float* z;    cudaGetSymbolAddress((void**)&z,    g_z);
    int*   cnt;  cudaGetSymbolAddress((void**)&cnt,  g_cnt);
    uint4* w4;   cudaGetSymbolAddress((void**)&w4,   g_w4);

    const int M = N_NODES;
    const int gemm_blocks = (M + 127) / 128;   // 391

    // ---- CSR build ----
    detect_k<<<1, 32>>>(ei);
    zero_int_k<<<(N_NODES + 255) / 256, 256>>>(cnt, N_NODES);
    count_k<<<(N_EDGES + 255) / 256, 256>>>(ei);
    scan1_k<<<NBLK, 256>>>();
    scan2_k<<<1, 256>>>();
    scan3_k<<<NBLK, 256>>>();
    fill_k<<<(N_EDGES + 255) / 256, 256>>>(ei);

    // ---- weight packing ----
    conv_w_k<<<16, 256>>>(W_in, IN_FEAT, w4);
    for (int l = 0; l < NUM_LAYERS; l++) {
        conv_w_k<<<16, 256>>>(W_nbr  + (size_t)l * HIDDEN * HIDDEN, HIDDEN, w4 + 2048 + l * 4096);
        conv_w_k<<<16, 256>>>(W_self + (size_t)l * HIDDEN * HIDDEN, HIDDEN, w4 + 2048 + (3 + l) * 4096);
    }

    // ---- input projection: hpkA = pack(x @ W_in + b_in) ----
    gemm_mma_k<IN_FEAT, 0, 2><<<gemm_blocks, 256>>>(x, w4, b_in, hpkA, M);

    const uint2* hcur = hpkA;
    for (int l = 0; l < NUM_LAYERS; l++) {
        const float* bs = b_self + (size_t)l * HIDDEN;
        const uint4* wn = w4 + 2048 + l * 4096;
        const uint4* ws = w4 + 2048 + (3 + l) * 4096;
        uint2* hnext = (hcur == hpkA) ? hpkB : hpkA;

        // t = h @ Wn ; z = h @ Ws + b
        gemm_mma_k<HIDDEN, 1, 0><<<gemm_blocks, 256>>>(hcur, wn, nullptr, t, M);
        gemm_mma_k<HIDDEN, 1, 1><<<gemm_blocks, 256>>>(hcur, ws, bs, z, M);
        // h' = elu(z + gather(t)/deg)
        if (l == NUM_LAYERS - 1)
            gather_fused_k<1><<<(N_NODES * 32 + 255) / 256, 256>>>(t, z, out);
        else
            gather_fused_k<0><<<(N_NODES * 32 + 255) / 256, 256>>>(t, z, hnext);

        hcur = hnext;
    }
}

// round 8
// speedup vs baseline: 1.1586x; 1.0497x over previous
#include <cuda_runtime.h>
#include <cuda_bf16.h>
#include <cuda_fp16.h>
#include <cstdint>

#define N_NODES   50000
#define IN_FEAT   64
#define HIDDEN    128
#define N_EDGES   800000
#define NUM_LAYERS 3
#define NBLK      ((N_NODES + 255) / 256)   // 196
#define HPAIRS    (HIDDEN / 2)              // 64 pairs per row

// ---------------- scratch (device globals; no allocation allowed) ------------
__device__ __align__(128) uint2   g_hpkA[N_NODES * HPAIRS];  // packed h (hi,lo bf16x2)
__device__ __align__(128) uint2   g_hpkB[N_NODES * HPAIRS];
__device__ __align__(128) __half2 g_t16 [N_NODES * HPAIRS];  // t in fp16 pairs
__device__ __align__(128) float   g_z   [N_NODES * HIDDEN];
__device__ int g_cnt   [N_NODES];
__device__ int g_offs  [N_NODES + 1];
__device__ int g_cursor[N_NODES];
__device__ int g_esrc  [N_EDGES];
__device__ int g_bsum  [NBLK];
__device__ int g_is64;
// interleaved fragment-major weights: uint4 {b0h,b1h,b0l,b1l}
// W_in: 2048 uint4 at 0; Wn[l]: 2048 + l*4096; Ws[l]: 2048 + (3+l)*4096
__device__ __align__(256) uint4 g_w4[2048 + 6 * 4096];

// ---------------- bf16 split helpers -----------------------------------------
__device__ __forceinline__ uint32_t pack_bf16x2(float x, float y) {
    uint32_t r;
    asm("cvt.rn.bf16x2.f32 %0, %1, %2;" : "=r"(r) : "f"(y), "f"(x));
    return r;
}
__device__ __forceinline__ void split2(float2 v, uint32_t& hi, uint32_t& lo) {
    hi = pack_bf16x2(v.x, v.y);
    float hx = __uint_as_float(hi << 16);
    float hy = __uint_as_float(hi & 0xFFFF0000u);
    lo = pack_bf16x2(v.x - hx, v.y - hy);
}
__device__ __forceinline__ void mma_bf16(float* c, const uint32_t* a, uint32_t b0, uint32_t b1) {
    asm volatile(
        "mma.sync.aligned.m16n8k16.row.col.f32.bf16.bf16.f32 "
        "{%0,%1,%2,%3}, {%4,%5,%6,%7}, {%8,%9}, {%0,%1,%2,%3};"
        : "+f"(c[0]), "+f"(c[1]), "+f"(c[2]), "+f"(c[3])
        : "r"(a[0]), "r"(a[1]), "r"(a[2]), "r"(a[3]), "r"(b0), "r"(b1));
}

// ---------------- index helpers ----------------------------------------------
__device__ __forceinline__ int load_src(const int* ei, int e, int is64) {
    return is64 ? ei[2 * e] : ei[e];
}
__device__ __forceinline__ int load_dst(const int* ei, int e, int is64) {
    return is64 ? ei[2 * (N_EDGES + e)] : ei[N_EDGES + e];
}

// ---------------- dtype detect -------------------------------------------------
__global__ void detect_k(const int* __restrict__ ei) {
    int lane = threadIdx.x;
    int bad = 0;
    for (int i = lane; i < 256; i += 32) bad |= (ei[2 * i + 1] != 0);
    bad = __any_sync(0xFFFFFFFFu, bad);
    if (lane == 0) g_is64 = !bad;
}

// ---------------- zero / count --------------------------------------------------
__global__ void zero_int_k(int* __restrict__ p, int n) {
    int i = blockIdx.x * blockDim.x + threadIdx.x;
    if (i < n) p[i] = 0;
}
__global__ void count_k(const int* __restrict__ ei) {
    int e = blockIdx.x * blockDim.x + threadIdx.x;
    if (e >= N_EDGES) return;
    atomicAdd(&g_cnt[load_dst(ei, e, g_is64)], 1);
}

// ---------------- 3-phase scan ----------------------------------------------------
__global__ __launch_bounds__(256) void scan1_k() {
    __shared__ int ws[8];
    int idx = blockIdx.x * 256 + threadIdx.x;
    int v = (idx < N_NODES) ? g_cnt[idx] : 0;
    int lane = threadIdx.x & 31, wid = threadIdx.x >> 5;
    for (int d = 16; d > 0; d >>= 1) v += __shfl_down_sync(0xFFFFFFFFu, v, d);
    if (lane == 0) ws[wid] = v;
    __syncthreads();
    if (threadIdx.x == 0) {
        int s = 0;
        for (int i = 0; i < 8; i++) s += ws[i];
        g_bsum[blockIdx.x] = s;
    }
}
__global__ __launch_bounds__(256) void scan2_k() {
    __shared__ int sh[256];
    int t = threadIdx.x;
    int v = (t < NBLK) ? g_bsum[t] : 0;
    sh[t] = v;
    __syncthreads();
    for (int d = 1; d < 256; d <<= 1) {
        int n = (t >= d) ? sh[t - d] : 0;
        __syncthreads();
        sh[t] += n;
        __syncthreads();
    }
    if (t < NBLK) g_bsum[t] = sh[t] - v;   // exclusive prefix
}
__global__ __launch_bounds__(256) void scan3_k() {
    __shared__ int sh[256];
    int t = threadIdx.x;
    int idx = blockIdx.x * 256 + t;
    int v = (idx < N_NODES) ? g_cnt[idx] : 0;
    sh[t] = v;
    __syncthreads();
    for (int d = 1; d < 256; d <<= 1) {
        int n = (t >= d) ? sh[t - d] : 0;
        __syncthreads();
        sh[t] += n;
        __syncthreads();
    }
    int ex = g_bsum[blockIdx.x] + sh[t] - v;
    if (idx < N_NODES) {
        g_offs[idx]   = ex;
        g_cursor[idx] = ex;
        if (idx == N_NODES - 1) g_offs[N_NODES] = ex + v;
    }
}

// ---------------- CSR fill --------------------------------------------------------
__global__ void fill_k(const int* __restrict__ ei) {
    int e = blockIdx.x * blockDim.x + threadIdx.x;
    if (e >= N_EDGES) return;
    int is64 = g_is64;
    int s = load_src(ei, e, is64);
    int d = load_dst(ei, e, is64);
    g_esrc[atomicAdd(&g_cursor[d], 1)] = s;
}

// ---------------- weight convert: W[K_,128] -> interleaved fragment uint4 ----------
__global__ void conv_w_k(const float* __restrict__ W, int K_, uint4* __restrict__ dst) {
    int NSTEP = K_ / 16;
    int total = 16 * NSTEP * 32;
    for (int idx = blockIdx.x * blockDim.x + threadIdx.x; idx < total;
         idx += gridDim.x * blockDim.x) {
        int lane = idx & 31;
        int s = (idx >> 5) % NSTEP;
        int J = idx / (NSTEP * 32);
        int t = lane & 3, g = lane >> 2;
        int k0 = s * 16 + t * 2;
        int k1 = k0 + 8;
        int n = J * 8 + g;
        uint32_t b0h, b0l, b1h, b1l;
        split2(make_float2(W[(size_t)k0 * HIDDEN + n], W[(size_t)(k0 + 1) * HIDDEN + n]), b0h, b0l);
        split2(make_float2(W[(size_t)k1 * HIDDEN + n], W[(size_t)(k1 + 1) * HIDDEN + n]), b1h, b1l);
        dst[idx] = make_uint4(b0h, b1h, b0l, b1l);
    }
}

// ---------------- input projection GEMM (fp32 A, packed-h out) ---------------------
__global__ __launch_bounds__(256, 2)
void gemm_in_k(const float* __restrict__ A,
               const uint4* __restrict__ B4,
               const float* __restrict__ bias,
               uint2* __restrict__ Cpk, int M) {
    constexpr int K_ = IN_FEAT, NSTEP = K_ / 16;
    const int tid  = threadIdx.x;
    const int warp = tid >> 5;
    const int lane = tid & 31;
    const int g = lane >> 2, t = lane & 3;
    const int warp_m = (warp & 3) * 32;
    const int warp_n = (warp >> 2) * 64;
    const int row_base = blockIdx.x * 128 + warp_m;

    float acc[2][8][4];
#pragma unroll
    for (int mt = 0; mt < 2; mt++)
#pragma unroll
        for (int j = 0; j < 8; j++)
#pragma unroll
            for (int q = 0; q < 4; q++) acc[mt][j][q] = 0.f;

#pragma unroll
    for (int s = 0; s < NSTEP; s++) {
        uint32_t ahi[2][4], alo[2][4];
        const int c0 = s * 16 + t * 2;
#pragma unroll
        for (int mt = 0; mt < 2; mt++) {
            int r0 = row_base + mt * 16 + g;
            int r1 = r0 + 8;
            float2 v00 = make_float2(0.f, 0.f), v10 = v00, v01 = v00, v11 = v00;
            if (r0 < M) {
                v00 = *(const float2*)(A + (size_t)r0 * K_ + c0);
                v01 = *(const float2*)(A + (size_t)r0 * K_ + c0 + 8);
            }
            if (r1 < M) {
                v10 = *(const float2*)(A + (size_t)r1 * K_ + c0);
                v11 = *(const float2*)(A + (size_t)r1 * K_ + c0 + 8);
            }
            split2(v00, ahi[mt][0], alo[mt][0]);
            split2(v10, ahi[mt][1], alo[mt][1]);
            split2(v01, ahi[mt][2], alo[mt][2]);
            split2(v11, ahi[mt][3], alo[mt][3]);
        }
#pragma unroll
        for (int j = 0; j < 8; j++) {
            int J = (warp >> 2) * 8 + j;
            uint4 b = B4[(size_t)(J * NSTEP + s) * 32 + lane];
#pragma unroll
            for (int mt = 0; mt < 2; mt++) {
                mma_bf16(acc[mt][j], ahi[mt], b.x, b.y);
                mma_bf16(acc[mt][j], ahi[mt], b.z, b.w);
                mma_bf16(acc[mt][j], alo[mt], b.x, b.y);
            }
        }
    }
#pragma unroll
    for (int j = 0; j < 8; j++) {
        int n0 = warp_n + j * 8 + t * 2;
        float2 bv = *(const float2*)(bias + n0);
#pragma unroll
        for (int mt = 0; mt < 2; mt++) {
            int r0 = row_base + mt * 16 + g;
            int r1 = r0 + 8;
            uint32_t h0, l0, h1, l1;
            split2(make_float2(acc[mt][j][0] + bv.x, acc[mt][j][1] + bv.y), h0, l0);
            split2(make_float2(acc[mt][j][2] + bv.x, acc[mt][j][3] + bv.y), h1, l1);
            if (r0 < M) Cpk[(size_t)r0 * HPAIRS + (n0 >> 1)] = make_uint2(h0, l0);
            if (r1 < M) Cpk[(size_t)r1 * HPAIRS + (n0 >> 1)] = make_uint2(h1, l1);
        }
    }
}

// ---------------- fused dual GEMM: t16 = h@Wn (fp16), z = h@Ws + bias (fp32) -------
// 512 threads = 16 warps (4m x 4n over N=256). A packed uint2.
__global__ __launch_bounds__(512, 1)
void gemm_dual_k(const uint2* __restrict__ Apk,
                 const uint4* __restrict__ Bn,   // Wn fragments (t output)
                 const uint4* __restrict__ Bs,   // Ws fragments (z output)
                 const float* __restrict__ bias,
                 __half2* __restrict__ Tout,
                 float* __restrict__ Zout, int M) {
    constexpr int NSTEP = HIDDEN / 16;  // 8
    const int tid  = threadIdx.x;
    const int warp = tid >> 5;
    const int lane = tid & 31;
    const int g = lane >> 2, t = lane & 3;
    const int warp_m  = (warp & 3) * 32;
    const int warp_n4 = warp >> 2;          // 0,1 -> t ; 2,3 -> z
    const int row_base = blockIdx.x * 128 + warp_m;

    const uint4* __restrict__ B4 = (warp_n4 < 2) ? Bn : Bs;
    const int Jbase = (warp_n4 & 1) * 8;

    float acc[2][8][4];
#pragma unroll
    for (int mt = 0; mt < 2; mt++)
#pragma unroll
        for (int j = 0; j < 8; j++)
#pragma unroll
            for (int q = 0; q < 4; q++) acc[mt][j][q] = 0.f;

#pragma unroll
    for (int s = 0; s < NSTEP; s++) {
        uint32_t ahi[2][4], alo[2][4];
        const int pr = s * 8 + t;
#pragma unroll
        for (int mt = 0; mt < 2; mt++) {
            int r0 = row_base + mt * 16 + g;
            int r1 = r0 + 8;
            uint2 zz = make_uint2(0u, 0u);
            uint2 p00 = zz, p01 = zz, p10 = zz, p11 = zz;
            if (r0 < M) {
                p00 = Apk[(size_t)r0 * HPAIRS + pr];
                p01 = Apk[(size_t)r0 * HPAIRS + pr + 4];
            }
            if (r1 < M) {
                p10 = Apk[(size_t)r1 * HPAIRS + pr];
                p11 = Apk[(size_t)r1 * HPAIRS + pr + 4];
            }
            ahi[mt][0] = p00.x; alo[mt][0] = p00.y;
            ahi[mt][1] = p10.x; alo[mt][1] = p10.y;
            ahi[mt][2] = p01.x; alo[mt][2] = p01.y;
            ahi[mt][3] = p11.x; alo[mt][3] = p11.y;
        }
#pragma unroll
        for (int j = 0; j < 8; j++) {
            int J = Jbase + j;
            uint4 b = B4[(size_t)(J * NSTEP + s) * 32 + lane];
#pragma unroll
            for (int mt = 0; mt < 2; mt++) {
                mma_bf16(acc[mt][j], ahi[mt], b.x, b.y);
                mma_bf16(acc[mt][j], ahi[mt], b.z, b.w);
                mma_bf16(acc[mt][j], alo[mt], b.x, b.y);
            }
        }
    }

    // epilogue
#pragma unroll
    for (int j = 0; j < 8; j++) {
        int n0 = (warp_n4 & 1) * 64 + j * 8 + t * 2;   // column within 128
        if (warp_n4 < 2) {
#pragma unroll
            for (int mt = 0; mt < 2; mt++) {
                int r0 = row_base + mt * 16 + g;
                int r1 = r0 + 8;
                if (r0 < M)
                    Tout[(size_t)r0 * HPAIRS + (n0 >> 1)] =
                        __float22half2_rn(make_float2(acc[mt][j][0], acc[mt][j][1]));
                if (r1 < M)
                    Tout[(size_t)r1 * HPAIRS + (n0 >> 1)] =
                        __float22half2_rn(make_float2(acc[mt][j][2], acc[mt][j][3]));
            }
        } else {
            float2 bv = *(const float2*)(bias + n0);
#pragma unroll
            for (int mt = 0; mt < 2; mt++) {
                int r0 = row_base + mt * 16 + g;
                int r1 = r0 + 8;
                if (r0 < M)
                    *(float2*)(Zout + (size_t)r0 * HIDDEN + n0) =
                        make_float2(acc[mt][j][0] + bv.x, acc[mt][j][1] + bv.y);
                if (r1 < M)
                    *(float2*)(Zout + (size_t)r1 * HIDDEN + n0) =
                        make_float2(acc[mt][j][2] + bv.x, acc[mt][j][3] + bv.y);
            }
        }
    }
}

// ---------------- fused gather + epilogue (t in fp16) -------------------------------
// r = elu( z[n] + (sum t[src])/max(deg,1) );  LAST: write fp32 out, else packed h
template <int LAST>
__global__ __launch_bounds__(256)
void gather_fused_k(const __half2* __restrict__ t16,
                    const float* __restrict__ z,
                    void* __restrict__ outv) {
    int gtid = blockIdx.x * blockDim.x + threadIdx.x;
    int node = gtid >> 5;
    if (node >= N_NODES) return;
    int lane = gtid & 31;
    int c = lane * 4;               // fp32 column base
    int p = lane * 2;               // half2 pair base

    int start = g_offs[node];
    int end   = g_offs[node + 1];

    float4 acc = make_float4(0.f, 0.f, 0.f, 0.f);
    int e = start;
    for (; e + 4 <= end; e += 4) {
        int s0 = g_esrc[e + 0], s1 = g_esrc[e + 1], s2 = g_esrc[e + 2], s3 = g_esrc[e + 3];
        uint2 q0 = __ldg((const uint2*)(t16 + (size_t)s0 * HPAIRS + p));
        uint2 q1 = __ldg((const uint2*)(t16 + (size_t)s1 * HPAIRS + p));
        uint2 q2 = __ldg((const uint2*)(t16 + (size_t)s2 * HPAIRS + p));
        uint2 q3 = __ldg((const uint2*)(t16 + (size_t)s3 * HPAIRS + p));
        float2 a0 = __half22float2(*(__half2*)&q0.x), b0 = __half22float2(*(__half2*)&q0.y);
        float2 a1 = __half22float2(*(__half2*)&q1.x), b1 = __half22float2(*(__half2*)&q1.y);
        float2 a2 = __half22float2(*(__half2*)&q2.x), b2 = __half22float2(*(__half2*)&q2.y);
        float2 a3 = __half22float2(*(__half2*)&q3.x), b3 = __half22float2(*(__half2*)&q3.y);
        acc.x += a0.x + a1.x + a2.x + a3.x;
        acc.y += a0.y + a1.y + a2.y + a3.y;
        acc.z += b0.x + b1.x + b2.x + b3.x;
        acc.w += b0.y + b1.y + b2.y + b3.y;
    }
    for (; e < end; e++) {
        int s = g_esrc[e];
        uint2 q = __ldg((const uint2*)(t16 + (size_t)s * HPAIRS + p));
        float2 a = __half22float2(*(__half2*)&q.x), b = __half22float2(*(__half2*)&q.y);
        acc.x += a.x; acc.y += a.y; acc.z += b.x; acc.w += b.y;
    }

    float inv = 1.0f / fmaxf((float)(end - start), 1.0f);
    float4 zv = __ldg((const float4*)(z + (size_t)node * HIDDEN + c));
    float4 r;
    r.x = zv.x + acc.x * inv;
    r.y = zv.y + acc.y * inv;
    r.z = zv.z + acc.z * inv;
    r.w = zv.w + acc.w * inv;
    r.x = (r.x > 0.f) ? r.x : expm1f(r.x);
    r.y = (r.y > 0.f) ? r.y : expm1f(r.y);
    r.z = (r.z > 0.f) ? r.z : expm1f(r.z);
    r.w = (r.w > 0.f) ? r.w : expm1f(r.w);

    if (LAST) {
        *(float4*)((float*)outv + (size_t)node * HIDDEN + c) = r;
    } else {
        uint32_t h0, l0, h1, l1;
        split2(make_float2(r.x, r.y), h0, l0);
        split2(make_float2(r.z, r.w), h1, l1);
        *(uint4*)((uint2*)outv + (size_t)node * HPAIRS + p) =
            make_uint4(h0, l0, h1, l1);
    }
}

// ---------------- launch ----------------------------------------------------------
extern "C" void kernel_launch(void* const* d_in, const int* in_sizes, int n_in,
                              void* d_out, int out_size) {
    const float* x      = (const float*)d_in[0];
    const int*   ei     = (const int*)d_in[1];
    const float* W_in   = (const float*)d_in[2];
    const float* b_in   = (const float*)d_in[3];
    const float* W_self = (const float*)d_in[4];
    const float* b_self = (const float*)d_in[5];
    const float* W_nbr  = (const float*)d_in[6];
    float*       out    = (float*)d_out;

    uint2*   hpkA; cudaGetSymbolAddress((void**)&hpkA, g_hpkA);
    uint2*   hpkB; cudaGetSymbolAddress((void**)&hpkB, g_hpkB);
    __half2* t16;  cudaGetSymbolAddress((void**)&t16,  g_t16);
    float*   z;    cudaGetSymbolAddress((void**)&z,    g_z);
    int*     cnt;  cudaGetSymbolAddress((void**)&cnt,  g_cnt);
    uint4*   w4;   cudaGetSymbolAddress((void**)&w4,   g_w4);

    const int M = N_NODES;
    const int gemm_blocks = (M + 127) / 128;   // 391

    // ---- CSR build ----
    detect_k<<<1, 32>>>(ei);
    zero_int_k<<<(N_NODES + 255) / 256, 256>>>(cnt, N_NODES);
    count_k<<<(N_EDGES + 255) / 256, 256>>>(ei);
    scan1_k<<<NBLK, 256>>>();
    scan2_k<<<1, 256>>>();
    scan3_k<<<NBLK, 256>>>();
    fill_k<<<(N_EDGES + 255) / 256, 256>>>(ei);

    // ---- weight packing ----
    conv_w_k<<<16, 256>>>(W_in, IN_FEAT, w4);
    for (int l = 0; l < NUM_LAYERS; l++) {
        conv_w_k<<<16, 256>>>(W_nbr  + (size_t)l * HIDDEN * HIDDEN, HIDDEN, w4 + 2048 + l * 4096);
        conv_w_k<<<16, 256>>>(W_self + (size_t)l * HIDDEN * HIDDEN, HIDDEN, w4 + 2048 + (3 + l) * 4096);
    }

    // ---- input projection: hpkA = pack(x @ W_in + b_in) ----
    gemm_in_k<<<gemm_blocks, 256>>>(x, w4, b_in, hpkA, M);

    const uint2* hcur = hpkA;
    for (int l = 0; l < NUM_LAYERS; l++) {
        const float* bs = b_self + (size_t)l * HIDDEN;
        const uint4* wn = w4 + 2048 + l * 4096;
        const uint4* ws = w4 + 2048 + (3 + l) * 4096;
        uint2* hnext = (hcur == hpkA) ? hpkB : hpkA;

        // t16 = h @ Wn (fp16) ; z = h @ Ws + b (fp32), one fused kernel
        gemm_dual_k<<<gemm_blocks, 512>>>(hcur, wn, ws, bs, t16, z, M);
        // h' = elu(z + gather(t)/deg)
        if (l == NUM_LAYERS - 1)
            gather_fused_k<1><<<(N_NODES * 32 + 255) / 256, 256>>>(t16, z, out);
        else
            gather_fused_k<0><<<(N_NODES * 32 + 255) / 256, 256>>>(t16, z, hnext);

        hcur = hnext;
    }
}

// round 9
// speedup vs baseline: 1.2802x; 1.1049x over previous
#include <cuda_runtime.h>
#include <cuda_fp16.h>
#include <cstdint>

#define N_NODES   50000
#define IN_FEAT   64
#define HIDDEN    128
#define N_EDGES   800000
#define NUM_LAYERS 3
#define NBLK      ((N_NODES + 255) / 256)   // 196
#define HPAIRS    (HIDDEN / 2)              // 64 pairs per row

// ---------------- scratch (device globals; no allocation allowed) ------------
__device__ __align__(128) uint2   g_hpkA[N_NODES * HPAIRS];  // packed h (hi,lo fp16x2)
__device__ __align__(128) uint2   g_hpkB[N_NODES * HPAIRS];
__device__ __align__(128) __half2 g_t16 [N_NODES * HPAIRS];  // t in fp16 pairs
__device__ __align__(128) float   g_z   [N_NODES * HIDDEN];
__device__ int g_cnt   [N_NODES];
__device__ int g_offs  [N_NODES + 1];
__device__ int g_cursor[N_NODES];
__device__ int g_esrc  [N_EDGES];
__device__ int g_bsum  [NBLK];
__device__ int g_is64;
// fp16 fragment-major weights: uint2 {b0,b1}
// W_in: 2048 at 0; Wn[l]: 2048 + l*4096; Ws[l]: 2048 + (3+l)*4096
__device__ __align__(256) uint2 g_w2[2048 + 6 * 4096];

// ---------------- fp16 split helpers -----------------------------------------
__device__ __forceinline__ uint32_t pack_h2(float x, float y) {
    __half2 h = __floats2half2_rn(x, y);
    return *(uint32_t*)&h;
}
// split float2 -> fp16 hi + fp16 residual lo (A = hi + lo to ~22 bits)
__device__ __forceinline__ void split2h(float2 v, uint32_t& hi, uint32_t& lo) {
    __half2 h = __floats2half2_rn(v.x, v.y);
    float2 hf = __half22float2(h);
    __half2 l = __floats2half2_rn(v.x - hf.x, v.y - hf.y);
    hi = *(uint32_t*)&h;
    lo = *(uint32_t*)&l;
}
__device__ __forceinline__ void mma_f16(float* c, const uint32_t* a, uint32_t b0, uint32_t b1) {
    asm volatile(
        "mma.sync.aligned.m16n8k16.row.col.f32.f16.f16.f32 "
        "{%0,%1,%2,%3}, {%4,%5,%6,%7}, {%8,%9}, {%0,%1,%2,%3};"
        : "+f"(c[0]), "+f"(c[1]), "+f"(c[2]), "+f"(c[3])
        : "r"(a[0]), "r"(a[1]), "r"(a[2]), "r"(a[3]), "r"(b0), "r"(b1));
}

// ---------------- index helpers ----------------------------------------------
__device__ __forceinline__ int load_src(const int* ei, int e, int is64) {
    return is64 ? ei[2 * e] : ei[e];
}
__device__ __forceinline__ int load_dst(const int* ei, int e, int is64) {
    return is64 ? ei[2 * (N_EDGES + e)] : ei[N_EDGES + e];
}

// ---------------- dtype detect -------------------------------------------------
__global__ void detect_k(const int* __restrict__ ei) {
    int lane = threadIdx.x;
    int bad = 0;
    for (int i = lane; i < 256; i += 32) bad |= (ei[2 * i + 1] != 0);
    bad = __any_sync(0xFFFFFFFFu, bad);
    if (lane == 0) g_is64 = !bad;
}

// ---------------- zero / count --------------------------------------------------
__global__ void zero_int_k(int* __restrict__ p, int n) {
    int i = blockIdx.x * blockDim.x + threadIdx.x;
    if (i < n) p[i] = 0;
}
__global__ void count_k(const int* __restrict__ ei) {
    int e = blockIdx.x * blockDim.x + threadIdx.x;
    if (e >= N_EDGES) return;
    atomicAdd(&g_cnt[load_dst(ei, e, g_is64)], 1);
}

// ---------------- 3-phase scan ----------------------------------------------------
__global__ __launch_bounds__(256) void scan1_k() {
    __shared__ int ws[8];
    int idx = blockIdx.x * 256 + threadIdx.x;
    int v = (idx < N_NODES) ? g_cnt[idx] : 0;
    int lane = threadIdx.x & 31, wid = threadIdx.x >> 5;
    for (int d = 16; d > 0; d >>= 1) v += __shfl_down_sync(0xFFFFFFFFu, v, d);
    if (lane == 0) ws[wid] = v;
    __syncthreads();
    if (threadIdx.x == 0) {
        int s = 0;
        for (int i = 0; i < 8; i++) s += ws[i];
        g_bsum[blockIdx.x] = s;
    }
}
__global__ __launch_bounds__(256) void scan2_k() {
    __shared__ int sh[256];
    int t = threadIdx.x;
    int v = (t < NBLK) ? g_bsum[t] : 0;
    sh[t] = v;
    __syncthreads();
    for (int d = 1; d < 256; d <<= 1) {
        int n = (t >= d) ? sh[t - d] : 0;
        __syncthreads();
        sh[t] += n;
        __syncthreads();
    }
    if (t < NBLK) g_bsum[t] = sh[t] - v;   // exclusive prefix
}
__global__ __launch_bounds__(256) void scan3_k() {
    __shared__ int sh[256];
    int t = threadIdx.x;
    int idx = blockIdx.x * 256 + t;
    int v = (idx < N_NODES) ? g_cnt[idx] : 0;
    sh[t] = v;
    __syncthreads();
    for (int d = 1; d < 256; d <<= 1) {
        int n = (t >= d) ? sh[t - d] : 0;
        __syncthreads();
        sh[t] += n;
        __syncthreads();
    }
    int ex = g_bsum[blockIdx.x] + sh[t] - v;
    if (idx < N_NODES) {
        g_offs[idx]   = ex;
        g_cursor[idx] = ex;
        if (idx == N_NODES - 1) g_offs[N_NODES] = ex + v;
    }
}

// ---------------- CSR fill --------------------------------------------------------
__global__ void fill_k(const int* __restrict__ ei) {
    int e = blockIdx.x * blockDim.x + threadIdx.x;
    if (e >= N_EDGES) return;
    int is64 = g_is64;
    int s = load_src(ei, e, is64);
    int d = load_dst(ei, e, is64);
    g_esrc[atomicAdd(&g_cursor[d], 1)] = s;
}

// ---------------- weight convert: W[K_,128] -> fp16 fragment uint2 -----------------
// one uint2 per (J, s, lane): {b0, b1}; t=lane&3, g=lane>>2
//   b0 = fp16{W[k0][n], W[k0+1][n]}, k0 = s*16 + t*2; b1 same at k1 = k0+8; n = J*8+g
__global__ void conv_w_k(const float* __restrict__ W, int K_, uint2* __restrict__ dst) {
    int NSTEP = K_ / 16;
    int total = 16 * NSTEP * 32;
    for (int idx = blockIdx.x * blockDim.x + threadIdx.x; idx < total;
         idx += gridDim.x * blockDim.x) {
        int lane = idx & 31;
        int s = (idx >> 5) % NSTEP;
        int J = idx / (NSTEP * 32);
        int t = lane & 3, g = lane >> 2;
        int k0 = s * 16 + t * 2;
        int k1 = k0 + 8;
        int n = J * 8 + g;
        uint32_t b0 = pack_h2(W[(size_t)k0 * HIDDEN + n], W[(size_t)(k0 + 1) * HIDDEN + n]);
        uint32_t b1 = pack_h2(W[(size_t)k1 * HIDDEN + n], W[(size_t)(k1 + 1) * HIDDEN + n]);
        dst[idx] = make_uint2(b0, b1);
    }
}

// ---------------- mma.sync GEMM ---------------------------------------------------
// C[M x 128] = A[M x K_] @ W. fp16 2-pass (A=hi+lo, B fp16), fp32 accumulate.
// 8 warps (4m x 2n), warp tile 32x64.
// APACK=1: A packed uint2 (hi,lo fp16x2). APACK=0: A fp32, split on the fly.
// OUTMODE 0: fp16 t-out   1: fp32 z-out + bias   2: packed h-out + bias
template <int K_, int APACK, int OUTMODE>
__global__ __launch_bounds__(256, 2)
void gemm_mma_k(const void* __restrict__ Av,
                const uint2* __restrict__ B2,
                const float* __restrict__ bias,
                void* __restrict__ Cv, int M) {
    constexpr int NSTEP = K_ / 16;
    const int tid  = threadIdx.x;
    const int warp = tid >> 5;
    const int lane = tid & 31;
    const int g = lane >> 2, t = lane & 3;
    const int warp_m = (warp & 3) * 32;
    const int warp_n = (warp >> 2) * 64;
    const int row_base = blockIdx.x * 128 + warp_m;

    float acc[2][8][4];
#pragma unroll
    for (int mt = 0; mt < 2; mt++)
#pragma unroll
        for (int j = 0; j < 8; j++)
#pragma unroll
            for (int q = 0; q < 4; q++) acc[mt][j][q] = 0.f;

#pragma unroll
    for (int s = 0; s < NSTEP; s++) {
        uint32_t ahi[2][4], alo[2][4];
        if (APACK) {
            const uint2* Apk = (const uint2*)Av;
            const int pr = s * 8 + t;
#pragma unroll
            for (int mt = 0; mt < 2; mt++) {
                int r0 = row_base + mt * 16 + g;
                int r1 = r0 + 8;
                uint2 zz = make_uint2(0u, 0u);
                uint2 p00 = zz, p01 = zz, p10 = zz, p11 = zz;
                if (r0 < M) {
                    p00 = Apk[(size_t)r0 * HPAIRS + pr];
                    p01 = Apk[(size_t)r0 * HPAIRS + pr + 4];
                }
                if (r1 < M) {
                    p10 = Apk[(size_t)r1 * HPAIRS + pr];
                    p11 = Apk[(size_t)r1 * HPAIRS + pr + 4];
                }
                ahi[mt][0] = p00.x; alo[mt][0] = p00.y;
                ahi[mt][1] = p10.x; alo[mt][1] = p10.y;
                ahi[mt][2] = p01.x; alo[mt][2] = p01.y;
                ahi[mt][3] = p11.x; alo[mt][3] = p11.y;
            }
        } else {
            const float* A = (const float*)Av;
            const int c0 = s * 16 + t * 2;
#pragma unroll
            for (int mt = 0; mt < 2; mt++) {
                int r0 = row_base + mt * 16 + g;
                int r1 = r0 + 8;
                float2 v00 = make_float2(0.f, 0.f), v10 = v00, v01 = v00, v11 = v00;
                if (r0 < M) {
                    v00 = *(const float2*)(A + (size_t)r0 * K_ + c0);
                    v01 = *(const float2*)(A + (size_t)r0 * K_ + c0 + 8);
                }
                if (r1 < M) {
                    v10 = *(const float2*)(A + (size_t)r1 * K_ + c0);
                    v11 = *(const float2*)(A + (size_t)r1 * K_ + c0 + 8);
                }
                split2h(v00, ahi[mt][0], alo[mt][0]);
                split2h(v10, ahi[mt][1], alo[mt][1]);
                split2h(v01, ahi[mt][2], alo[mt][2]);
                split2h(v11, ahi[mt][3], alo[mt][3]);
            }
        }
#pragma unroll
        for (int j = 0; j < 8; j++) {
            int J = (warp >> 2) * 8 + j;
            uint2 b = B2[(size_t)(J * NSTEP + s) * 32 + lane];
#pragma unroll
            for (int mt = 0; mt < 2; mt++) {
                mma_f16(acc[mt][j], ahi[mt], b.x, b.y);   // hi * B
                mma_f16(acc[mt][j], alo[mt], b.x, b.y);   // lo * B (correction)
            }
        }
    }

    // epilogue
#pragma unroll
    for (int j = 0; j < 8; j++) {
        int n0 = warp_n + j * 8 + t * 2;
        float2 bv = make_float2(0.f, 0.f);
        if (OUTMODE >= 1) bv = *(const float2*)(bias + n0);
#pragma unroll
        for (int mt = 0; mt < 2; mt++) {
            int r0 = row_base + mt * 16 + g;
            int r1 = r0 + 8;
            float vx0 = acc[mt][j][0] + bv.x, vy0 = acc[mt][j][1] + bv.y;
            float vx1 = acc[mt][j][2] + bv.x, vy1 = acc[mt][j][3] + bv.y;
            if (OUTMODE == 0) {
                __half2* T = (__half2*)Cv;
                if (r0 < M) T[(size_t)r0 * HPAIRS + (n0 >> 1)] = __floats2half2_rn(vx0, vy0);
                if (r1 < M) T[(size_t)r1 * HPAIRS + (n0 >> 1)] = __floats2half2_rn(vx1, vy1);
            } else if (OUTMODE == 1) {
                float* C = (float*)Cv;
                if (r0 < M) *(float2*)(C + (size_t)r0 * HIDDEN + n0) = make_float2(vx0, vy0);
                if (r1 < M) *(float2*)(C + (size_t)r1 * HIDDEN + n0) = make_float2(vx1, vy1);
            } else {
                uint2* Cpk = (uint2*)Cv;
                uint32_t h0, l0, h1, l1;
                split2h(make_float2(vx0, vy0), h0, l0);
                split2h(make_float2(vx1, vy1), h1, l1);
                if (r0 < M) Cpk[(size_t)r0 * HPAIRS + (n0 >> 1)] = make_uint2(h0, l0);
                if (r1 < M) Cpk[(size_t)r1 * HPAIRS + (n0 >> 1)] = make_uint2(h1, l1);
            }
        }
    }
}

// ---------------- fused gather + epilogue (t in fp16) -------------------------------
// r = elu( z[n] + (sum t[src])/max(deg,1) );  LAST: write fp32 out, else packed h
template <int LAST>
__global__ __launch_bounds__(256)
void gather_fused_k(const __half2* __restrict__ t16,
                    const float* __restrict__ z,
                    void* __restrict__ outv) {
    int gtid = blockIdx.x * blockDim.x + threadIdx.x;
    int node = gtid >> 5;
    if (node >= N_NODES) return;
    int lane = gtid & 31;
    int c = lane * 4;               // fp32 column base
    int p = lane * 2;               // half2 pair base

    int start = g_offs[node];
    int end   = g_offs[node + 1];

    float4 acc = make_float4(0.f, 0.f, 0.f, 0.f);
    int e = start;
    for (; e + 4 <= end; e += 4) {
        int s0 = g_esrc[e + 0], s1 = g_esrc[e + 1], s2 = g_esrc[e + 2], s3 = g_esrc[e + 3];
        uint2 q0 = __ldg((const uint2*)(t16 + (size_t)s0 * HPAIRS + p));
        uint2 q1 = __ldg((const uint2*)(t16 + (size_t)s1 * HPAIRS + p));
        uint2 q2 = __ldg((const uint2*)(t16 + (size_t)s2 * HPAIRS + p));
        uint2 q3 = __ldg((const uint2*)(t16 + (size_t)s3 * HPAIRS + p));
        float2 a0 = __half22float2(*(__half2*)&q0.x), b0 = __half22float2(*(__half2*)&q0.y);
        float2 a1 = __half22float2(*(__half2*)&q1.x), b1 = __half22float2(*(__half2*)&q1.y);
        float2 a2 = __half22float2(*(__half2*)&q2.x), b2 = __half22float2(*(__half2*)&q2.y);
        float2 a3 = __half22float2(*(__half2*)&q3.x), b3 = __half22float2(*(__half2*)&q3.y);
        acc.x += a0.x + a1.x + a2.x + a3.x;
        acc.y += a0.y + a1.y + a2.y + a3.y;
        acc.z += b0.x + b1.x + b2.x + b3.x;
        acc.w += b0.y + b1.y + b2.y + b3.y;
    }
    for (; e < end; e++) {
        int s = g_esrc[e];
        uint2 q = __ldg((const uint2*)(t16 + (size_t)s * HPAIRS + p));
        float2 a = __half22float2(*(__half2*)&q.x), b = __half22float2(*(__half2*)&q.y);
        acc.x += a.x; acc.y += a.y; acc.z += b.x; acc.w += b.y;
    }

    float inv = 1.0f / fmaxf((float)(end - start), 1.0f);
    float4 zv = __ldg((const float4*)(z + (size_t)node * HIDDEN + c));
    float4 r;
    r.x = zv.x + acc.x * inv;
    r.y = zv.y + acc.y * inv;
    r.z = zv.z + acc.z * inv;
    r.w = zv.w + acc.w * inv;
    r.x = (r.x > 0.f) ? r.x : expm1f(r.x);
    r.y = (r.y > 0.f) ? r.y : expm1f(r.y);
    r.z = (r.z > 0.f) ? r.z : expm1f(r.z);
    r.w = (r.w > 0.f) ? r.w : expm1f(r.w);

    if (LAST) {
        *(float4*)((float*)outv + (size_t)node * HIDDEN + c) = r;
    } else {
        uint32_t h0, l0, h1, l1;
        split2h(make_float2(r.x, r.y), h0, l0);
        split2h(make_float2(r.z, r.w), h1, l1);
        *(uint4*)((uint2*)outv + (size_t)node * HPAIRS + p) =
            make_uint4(h0, l0, h1, l1);
    }
}

// ---------------- launch ----------------------------------------------------------
extern "C" void kernel_launch(void* const* d_in, const int* in_sizes, int n_in,
                              void* d_out, int out_size) {
    const float* x      = (const float*)d_in[0];
    const int*   ei     = (const int*)d_in[1];
    const float* W_in   = (const float*)d_in[2];
    const float* b_in   = (const float*)d_in[3];
    const float* W_self = (const float*)d_in[4];
    const float* b_self = (const float*)d_in[5];
    const float* W_nbr  = (const float*)d_in[6];
    float*       out    = (float*)d_out;

    uint2*   hpkA; cudaGetSymbolAddress((void**)&hpkA, g_hpkA);
    uint2*   hpkB; cudaGetSymbolAddress((void**)&hpkB, g_hpkB);
    __half2* t16;  cudaGetSymbolAddress((void**)&t16,  g_t16);
    float*   z;    cudaGetSymbolAddress((void**)&z,    g_z);
    int*     cnt;  cudaGetSymbolAddress((void**)&cnt,  g_cnt);
    uint2*   w2;   cudaGetSymbolAddress((void**)&w2,   g_w2);

    const int M = N_NODES;
    const int gemm_blocks = (M + 127) / 128;   // 391

    // ---- CSR build ----
    detect_k<<<1, 32>>>(ei);
    zero_int_k<<<(N_NODES + 255) / 256, 256>>>(cnt, N_NODES);
    count_k<<<(N_EDGES + 255) / 256, 256>>>(ei);
    scan1_k<<<NBLK, 256>>>();
    scan2_k<<<1, 256>>>();
    scan3_k<<<NBLK, 256>>>();
    fill_k<<<(N_EDGES + 255) / 256, 256>>>(ei);

    // ---- weight packing (fp16 fragments) ----
    conv_w_k<<<16, 256>>>(W_in, IN_FEAT, w2);
    for (int l = 0; l < NUM_LAYERS; l++) {
        conv_w_k<<<16, 256>>>(W_nbr  + (size_t)l * HIDDEN * HIDDEN, HIDDEN, w2 + 2048 + l * 4096);
        conv_w_k<<<16, 256>>>(W_self + (size_t)l * HIDDEN * HIDDEN, HIDDEN, w2 + 2048 + (3 + l) * 4096);
    }

    // ---- input projection: hpkA = pack(x @ W_in + b_in) ----
    gemm_mma_k<IN_FEAT, 0, 2><<<gemm_blocks, 256>>>(x, w2, b_in, hpkA, M);

    const uint2* hcur = hpkA;
    for (int l = 0; l < NUM_LAYERS; l++) {
        const float* bs = b_self + (size_t)l * HIDDEN;
        const uint2* wn = w2 + 2048 + l * 4096;
        const uint2* ws = w2 + 2048 + (3 + l) * 4096;
        uint2* hnext = (hcur == hpkA) ? hpkB : hpkA;

        // t16 = h @ Wn (fp16) ; z = h @ Ws + b (fp32)
        gemm_mma_k<HIDDEN, 1, 0><<<gemm_blocks, 256>>>(hcur, wn, nullptr, t16, M);
        gemm_mma_k<HIDDEN, 1, 1><<<gemm_blocks, 256>>>(hcur, ws, bs, z, M);
        // h' = elu(z + gather(t)/deg)
        if (l == NUM_LAYERS - 1)
            gather_fused_k<1><<<(N_NODES * 32 + 255) / 256, 256>>>(t16, z, out);
        else
            gather_fused_k<0><<<(N_NODES * 32 + 255) / 256, 256>>>(t16, z, hnext);

        hcur = hnext;
    }
}

// round 10
// speedup vs baseline: 1.3928x; 1.0880x over previous
#include <cuda_runtime.h>
#include <cuda_fp16.h>
#include <cstdint>

#define N_NODES   50000
#define IN_FEAT   64
#define HIDDEN    128
#define N_EDGES   800000
#define NUM_LAYERS 3
#define NBLK      ((N_NODES + 255) / 256)   // 196
#define HPAIRS    (HIDDEN / 2)              // 64 pairs per row

// ---------------- scratch (device globals; no allocation allowed) ------------
__device__ __align__(128) uint2   g_hpkA[N_NODES * HPAIRS];  // packed h (hi,lo fp16x2)
__device__ __align__(128) uint2   g_hpkB[N_NODES * HPAIRS];
__device__ __align__(128) __half2 g_t16 [N_NODES * HPAIRS];  // t in fp16 pairs
__device__ __align__(128) float   g_z   [N_NODES * HIDDEN];
__device__ int g_cnt   [N_NODES];
__device__ int g_offs  [N_NODES + 1];
__device__ int g_cursor[N_NODES];
__device__ int g_esrc  [N_EDGES];
__device__ int g_bsum  [NBLK];
__device__ int g_is64;
// fp16 fragment-major weights: uint2 {b0,b1}
// W_in: 2048 at 0; Wn[l]: 2048 + l*4096; Ws[l]: 2048 + (3+l)*4096
__device__ __align__(256) uint2 g_w2[2048 + 6 * 4096];

// ---------------- fp16 split helpers -----------------------------------------
__device__ __forceinline__ uint32_t pack_h2(float x, float y) {
    __half2 h = __floats2half2_rn(x, y);
    return *(uint32_t*)&h;
}
// split float2 -> fp16 hi + fp16 residual lo (A = hi + lo to ~22 bits)
__device__ __forceinline__ void split2h(float2 v, uint32_t& hi, uint32_t& lo) {
    __half2 h = __floats2half2_rn(v.x, v.y);
    float2 hf = __half22float2(h);
    __half2 l = __floats2half2_rn(v.x - hf.x, v.y - hf.y);
    hi = *(uint32_t*)&h;
    lo = *(uint32_t*)&l;
}
__device__ __forceinline__ void mma_f16(float* c, const uint32_t* a, uint32_t b0, uint32_t b1) {
    asm volatile(
        "mma.sync.aligned.m16n8k16.row.col.f32.f16.f16.f32 "
        "{%0,%1,%2,%3}, {%4,%5,%6,%7}, {%8,%9}, {%0,%1,%2,%3};"
        : "+f"(c[0]), "+f"(c[1]), "+f"(c[2]), "+f"(c[3])
        : "r"(a[0]), "r"(a[1]), "r"(a[2]), "r"(a[3]), "r"(b0), "r"(b1));
}

// ---------------- index helpers ----------------------------------------------
__device__ __forceinline__ int load_src(const int* ei, int e, int is64) {
    return is64 ? ei[2 * e] : ei[e];
}
__device__ __forceinline__ int load_dst(const int* ei, int e, int is64) {
    return is64 ? ei[2 * (N_EDGES + e)] : ei[N_EDGES + e];
}

// ---------------- dtype detect -------------------------------------------------
__global__ void detect_k(const int* __restrict__ ei) {
    int lane = threadIdx.x;
    int bad = 0;
    for (int i = lane; i < 256; i += 32) bad |= (ei[2 * i + 1] != 0);
    bad = __any_sync(0xFFFFFFFFu, bad);
    if (lane == 0) g_is64 = !bad;
}

// ---------------- count ----------------------------------------------------------
__global__ void count_k(const int* __restrict__ ei) {
    int e = blockIdx.x * blockDim.x + threadIdx.x;
    if (e >= N_EDGES) return;
    atomicAdd(&g_cnt[load_dst(ei, e, g_is64)], 1);
}

// ---------------- 3-phase scan ----------------------------------------------------
__global__ __launch_bounds__(256) void scan1_k() {
    __shared__ int ws[8];
    int idx = blockIdx.x * 256 + threadIdx.x;
    int v = (idx < N_NODES) ? g_cnt[idx] : 0;
    int lane = threadIdx.x & 31, wid = threadIdx.x >> 5;
    for (int d = 16; d > 0; d >>= 1) v += __shfl_down_sync(0xFFFFFFFFu, v, d);
    if (lane == 0) ws[wid] = v;
    __syncthreads();
    if (threadIdx.x == 0) {
        int s = 0;
        for (int i = 0; i < 8; i++) s += ws[i];
        g_bsum[blockIdx.x] = s;
    }
}
__global__ __launch_bounds__(256) void scan2_k() {
    __shared__ int sh[256];
    int t = threadIdx.x;
    int v = (t < NBLK) ? g_bsum[t] : 0;
    sh[t] = v;
    __syncthreads();
    for (int d = 1; d < 256; d <<= 1) {
        int n = (t >= d) ? sh[t - d] : 0;
        __syncthreads();
        sh[t] += n;
        __syncthreads();
    }
    if (t < NBLK) g_bsum[t] = sh[t] - v;   // exclusive prefix
}
__global__ __launch_bounds__(256) void scan3_k() {
    __shared__ int sh[256];
    int t = threadIdx.x;
    int idx = blockIdx.x * 256 + t;
    int v = (idx < N_NODES) ? g_cnt[idx] : 0;
    sh[t] = v;
    __syncthreads();
    for (int d = 1; d < 256; d <<= 1) {
        int n = (t >= d) ? sh[t - d] : 0;
        __syncthreads();
        sh[t] += n;
        __syncthreads();
    }
    int ex = g_bsum[blockIdx.x] + sh[t] - v;
    if (idx < N_NODES) {
        g_offs[idx]   = ex;
        g_cursor[idx] = ex;
        if (idx == N_NODES - 1) g_offs[N_NODES] = ex + v;
    }
}

// ---------------- CSR fill --------------------------------------------------------
__global__ void fill_k(const int* __restrict__ ei) {
    int e = blockIdx.x * blockDim.x + threadIdx.x;
    if (e >= N_EDGES) return;
    int is64 = g_is64;
    int s = load_src(ei, e, is64);
    int d = load_dst(ei, e, is64);
    g_esrc[atomicAdd(&g_cursor[d], 1)] = s;
}

// ---------------- weight convert: ALL weights in one kernel ------------------------
// fragment layout per weight: one uint2 per (J, s, lane): {b0,b1}; t=lane&3, g=lane>>2
//   b0 = fp16{W[k0][n], W[k0+1][n]}, k0 = s*16 + t*2; b1 at k1 = k0+8; n = J*8+g
// index space: [0,2048) -> W_in (NSTEP=4); then 6 slots of 4096 (NSTEP=8):
//   slot 0..2 = Wn[l], slot 3..5 = Ws[l-3]
__global__ void conv_all_k(const float* __restrict__ W_in,
                           const float* __restrict__ W_nbr,
                           const float* __restrict__ W_self) {
    constexpr int TOTAL = 2048 + 6 * 4096;
    for (int idx = blockIdx.x * blockDim.x + threadIdx.x; idx < TOTAL;
         idx += gridDim.x * blockDim.x) {
        const float* W;
        int NSTEP, local;
        if (idx < 2048) {
            W = W_in; NSTEP = 4; local = idx;
        } else {
            int slot = (idx - 2048) / 4096;
            local = (idx - 2048) % 4096;
            NSTEP = 8;
            W = (slot < 3) ? (W_nbr  + (size_t)slot * HIDDEN * HIDDEN)
                           : (W_self + (size_t)(slot - 3) * HIDDEN * HIDDEN);
        }
        int lane = local & 31;
        int s = (local >> 5) % NSTEP;
        int J = local / (NSTEP * 32);
        int t = lane & 3, g = lane >> 2;
        int k0 = s * 16 + t * 2;
        int k1 = k0 + 8;
        int n = J * 8 + g;
        uint32_t b0 = pack_h2(W[(size_t)k0 * HIDDEN + n], W[(size_t)(k0 + 1) * HIDDEN + n]);
        uint32_t b1 = pack_h2(W[(size_t)k1 * HIDDEN + n], W[(size_t)(k1 + 1) * HIDDEN + n]);
        g_w2[idx] = make_uint2(b0, b1);
    }
}

// ---------------- input projection GEMM (fp32 A -> packed h out) -------------------
__global__ __launch_bounds__(256, 2)
void gemm_in_k(const float* __restrict__ A,
               const uint2* __restrict__ B2,
               const float* __restrict__ bias,
               uint2* __restrict__ Cpk, int M) {
    constexpr int K_ = IN_FEAT, NSTEP = K_ / 16;
    const int tid  = threadIdx.x;
    const int warp = tid >> 5;
    const int lane = tid & 31;
    const int g = lane >> 2, t = lane & 3;
    const int warp_m = (warp & 3) * 32;
    const int warp_n = (warp >> 2) * 64;
    const int row_base = blockIdx.x * 128 + warp_m;

    float acc[2][8][4];
#pragma unroll
    for (int mt = 0; mt < 2; mt++)
#pragma unroll
        for (int j = 0; j < 8; j++)
#pragma unroll
            for (int q = 0; q < 4; q++) acc[mt][j][q] = 0.f;

#pragma unroll
    for (int s = 0; s < NSTEP; s++) {
        uint32_t ahi[2][4], alo[2][4];
        const int c0 = s * 16 + t * 2;
#pragma unroll
        for (int mt = 0; mt < 2; mt++) {
            int r0 = row_base + mt * 16 + g;
            int r1 = r0 + 8;
            float2 v00 = make_float2(0.f, 0.f), v10 = v00, v01 = v00, v11 = v00;
            if (r0 < M) {
                v00 = *(const float2*)(A + (size_t)r0 * K_ + c0);
                v01 = *(const float2*)(A + (size_t)r0 * K_ + c0 + 8);
            }
            if (r1 < M) {
                v10 = *(const float2*)(A + (size_t)r1 * K_ + c0);
                v11 = *(const float2*)(A + (size_t)r1 * K_ + c0 + 8);
            }
            split2h(v00, ahi[mt][0], alo[mt][0]);
            split2h(v10, ahi[mt][1], alo[mt][1]);
            split2h(v01, ahi[mt][2], alo[mt][2]);
            split2h(v11, ahi[mt][3], alo[mt][3]);
        }
#pragma unroll
        for (int j = 0; j < 8; j++) {
            int J = (warp >> 2) * 8 + j;
            uint2 b = B2[(size_t)(J * NSTEP + s) * 32 + lane];
#pragma unroll
            for (int mt = 0; mt < 2; mt++) {
                mma_f16(acc[mt][j], ahi[mt], b.x, b.y);
                mma_f16(acc[mt][j], alo[mt], b.x, b.y);
            }
        }
    }
#pragma unroll
    for (int j = 0; j < 8; j++) {
        int n0 = warp_n + j * 8 + t * 2;
        float2 bv = *(const float2*)(bias + n0);
#pragma unroll
        for (int mt = 0; mt < 2; mt++) {
            int r0 = row_base + mt * 16 + g;
            int r1 = r0 + 8;
            uint32_t h0, l0, h1, l1;
            split2h(make_float2(acc[mt][j][0] + bv.x, acc[mt][j][1] + bv.y), h0, l0);
            split2h(make_float2(acc[mt][j][2] + bv.x, acc[mt][j][3] + bv.y), h1, l1);
            if (r0 < M) Cpk[(size_t)r0 * HPAIRS + (n0 >> 1)] = make_uint2(h0, l0);
            if (r1 < M) Cpk[(size_t)r1 * HPAIRS + (n0 >> 1)] = make_uint2(h1, l1);
        }
    }
}

// ---------------- dual layer GEMM: one launch, grid (391, 2) -----------------------
// blockIdx.y == 0: Tout = A @ Wn   (fp16 out)
// blockIdx.y == 1: Zout = A @ Ws + bias (fp32 out)
// A packed uint2 (hi,lo fp16x2). fp16 2-pass, fp32 accumulate.
__global__ __launch_bounds__(256, 2)
void gemm_layer_k(const uint2* __restrict__ Apk,
                  const uint2* __restrict__ Bn,
                  const uint2* __restrict__ Bs,
                  const float* __restrict__ bias,
                  __half2* __restrict__ Tout,
                  float* __restrict__ Zout, int M) {
    constexpr int NSTEP = HIDDEN / 16;  // 8
    const int tid  = threadIdx.x;
    const int warp = tid >> 5;
    const int lane = tid & 31;
    const int g = lane >> 2, t = lane & 3;
    const int warp_m = (warp & 3) * 32;
    const int warp_n = (warp >> 2) * 64;
    const int row_base = blockIdx.x * 128 + warp_m;
    const bool is_z = (blockIdx.y != 0);
    const uint2* __restrict__ B2 = is_z ? Bs : Bn;

    float acc[2][8][4];
#pragma unroll
    for (int mt = 0; mt < 2; mt++)
#pragma unroll
        for (int j = 0; j < 8; j++)
#pragma unroll
            for (int q = 0; q < 4; q++) acc[mt][j][q] = 0.f;

#pragma unroll
    for (int s = 0; s < NSTEP; s++) {
        uint32_t ahi[2][4], alo[2][4];
        const int pr = s * 8 + t;
#pragma unroll
        for (int mt = 0; mt < 2; mt++) {
            int r0 = row_base + mt * 16 + g;
            int r1 = r0 + 8;
            uint2 zz = make_uint2(0u, 0u);
            uint2 p00 = zz, p01 = zz, p10 = zz, p11 = zz;
            if (r0 < M) {
                p00 = Apk[(size_t)r0 * HPAIRS + pr];
                p01 = Apk[(size_t)r0 * HPAIRS + pr + 4];
            }
            if (r1 < M) {
                p10 = Apk[(size_t)r1 * HPAIRS + pr];
                p11 = Apk[(size_t)r1 * HPAIRS + pr + 4];
            }
            ahi[mt][0] = p00.x; alo[mt][0] = p00.y;
            ahi[mt][1] = p10.x; alo[mt][1] = p10.y;
            ahi[mt][2] = p01.x; alo[mt][2] = p01.y;
            ahi[mt][3] = p11.x; alo[mt][3] = p11.y;
        }
#pragma unroll
        for (int j = 0; j < 8; j++) {
            int J = (warp >> 2) * 8 + j;
            uint2 b = B2[(size_t)(J * NSTEP + s) * 32 + lane];
#pragma unroll
            for (int mt = 0; mt < 2; mt++) {
                mma_f16(acc[mt][j], ahi[mt], b.x, b.y);
                mma_f16(acc[mt][j], alo[mt], b.x, b.y);
            }
        }
    }

    // epilogue
    if (is_z) {
#pragma unroll
        for (int j = 0; j < 8; j++) {
            int n0 = warp_n + j * 8 + t * 2;
            float2 bv = *(const float2*)(bias + n0);
#pragma unroll
            for (int mt = 0; mt < 2; mt++) {
                int r0 = row_base + mt * 16 + g;
                int r1 = r0 + 8;
                if (r0 < M)
                    *(float2*)(Zout + (size_t)r0 * HIDDEN + n0) =
                        make_float2(acc[mt][j][0] + bv.x, acc[mt][j][1] + bv.y);
                if (r1 < M)
                    *(float2*)(Zout + (size_t)r1 * HIDDEN + n0) =
                        make_float2(acc[mt][j][2] + bv.x, acc[mt][j][3] + bv.y);
            }
        }
    } else {
#pragma unroll
        for (int j = 0; j < 8; j++) {
            int n0 = warp_n + j * 8 + t * 2;
#pragma unroll
            for (int mt = 0; mt < 2; mt++) {
                int r0 = row_base + mt * 16 + g;
                int r1 = r0 + 8;
                if (r0 < M)
                    Tout[(size_t)r0 * HPAIRS + (n0 >> 1)] =
                        __floats2half2_rn(acc[mt][j][0], acc[mt][j][1]);
                if (r1 < M)
                    Tout[(size_t)r1 * HPAIRS + (n0 >> 1)] =
                        __floats2half2_rn(acc[mt][j][2], acc[mt][j][3]);
            }
        }
    }
}

// ---------------- fused gather + epilogue (t in fp16) -------------------------------
// r = elu( z[n] + (sum t[src])/max(deg,1) );  LAST: write fp32 out, else packed h
template <int LAST>
__global__ __launch_bounds__(256)
void gather_fused_k(const __half2* __restrict__ t16,
                    const float* __restrict__ z,
                    void* __restrict__ outv) {
    int gtid = blockIdx.x * blockDim.x + threadIdx.x;
    int node = gtid >> 5;
    if (node >= N_NODES) return;
    int lane = gtid & 31;
    int c = lane * 4;               // fp32 column base
    int p = lane * 2;               // half2 pair base

    int start = g_offs[node];
    int end   = g_offs[node + 1];

    float4 acc = make_float4(0.f, 0.f, 0.f, 0.f);
    int e = start;
    for (; e + 4 <= end; e += 4) {
        int s0 = g_esrc[e + 0], s1 = g_esrc[e + 1], s2 = g_esrc[e + 2], s3 = g_esrc[e + 3];
        uint2 q0 = __ldg((const uint2*)(t16 + (size_t)s0 * HPAIRS + p));
        uint2 q1 = __ldg((const uint2*)(t16 + (size_t)s1 * HPAIRS + p));
        uint2 q2 = __ldg((const uint2*)(t16 + (size_t)s2 * HPAIRS + p));
        uint2 q3 = __ldg((const uint2*)(t16 + (size_t)s3 * HPAIRS + p));
        float2 a0 = __half22float2(*(__half2*)&q0.x), b0 = __half22float2(*(__half2*)&q0.y);
        float2 a1 = __half22float2(*(__half2*)&q1.x), b1 = __half22float2(*(__half2*)&q1.y);
        float2 a2 = __half22float2(*(__half2*)&q2.x), b2 = __half22float2(*(__half2*)&q2.y);
        float2 a3 = __half22float2(*(__half2*)&q3.x), b3 = __half22float2(*(__half2*)&q3.y);
        acc.x += a0.x + a1.x + a2.x + a3.x;
        acc.y += a0.y + a1.y + a2.y + a3.y;
        acc.z += b0.x + b1.x + b2.x + b3.x;
        acc.w += b0.y + b1.y + b2.y + b3.y;
    }
    for (; e < end; e++) {
        int s = g_esrc[e];
        uint2 q = __ldg((const uint2*)(t16 + (size_t)s * HPAIRS + p));
        float2 a = __half22float2(*(__half2*)&q.x), b = __half22float2(*(__half2*)&q.y);
        acc.x += a.x; acc.y += a.y; acc.z += b.x; acc.w += b.y;
    }

    float inv = 1.0f / fmaxf((float)(end - start), 1.0f);
    float4 zv = __ldg((const float4*)(z + (size_t)node * HIDDEN + c));
    float4 r;
    r.x = zv.x + acc.x * inv;
    r.y = zv.y + acc.y * inv;
    r.z = zv.z + acc.z * inv;
    r.w = zv.w + acc.w * inv;
    r.x = (r.x > 0.f) ? r.x : expm1f(r.x);
    r.y = (r.y > 0.f) ? r.y : expm1f(r.y);
    r.z = (r.z > 0.f) ? r.z : expm1f(r.z);
    r.w = (r.w > 0.f) ? r.w : expm1f(r.w);

    if (LAST) {
        *(float4*)((float*)outv + (size_t)node * HIDDEN + c) = r;
    } else {
        uint32_t h0, l0, h1, l1;
        split2h(make_float2(r.x, r.y), h0, l0);
        split2h(make_float2(r.z, r.w), h1, l1);
        *(uint4*)((uint2*)outv + (size_t)node * HPAIRS + p) =
            make_uint4(h0, l0, h1, l1);
    }
}

// ---------------- launch ----------------------------------------------------------
extern "C" void kernel_launch(void* const* d_in, const int* in_sizes, int n_in,
                              void* d_out, int out_size) {
    const float* x      = (const float*)d_in[0];
    const int*   ei     = (const int*)d_in[1];
    const float* W_in   = (const float*)d_in[2];
    const float* b_in   = (const float*)d_in[3];
    const float* W_self = (const float*)d_in[4];
    const float* b_self = (const float*)d_in[5];
    const float* W_nbr  = (const float*)d_in[6];
    float*       out    = (float*)d_out;

    uint2*   hpkA; cudaGetSymbolAddress((void**)&hpkA, g_hpkA);
    uint2*   hpkB; cudaGetSymbolAddress((void**)&hpkB, g_hpkB);
    __half2* t16;  cudaGetSymbolAddress((void**)&t16,  g_t16);
    float*   z;    cudaGetSymbolAddress((void**)&z,    g_z);
    int*     cnt;  cudaGetSymbolAddress((void**)&cnt,  g_cnt);
    uint2*   w2;   cudaGetSymbolAddress((void**)&w2,   g_w2);

    const int M = N_NODES;
    const int gemm_blocks = (M + 127) / 128;   // 391

    // ---- CSR build ----
    detect_k<<<1, 32>>>(ei);
    cudaMemsetAsync(cnt, 0, N_NODES * sizeof(int));
    count_k<<<(N_EDGES + 255) / 256, 256>>>(ei);
    scan1_k<<<NBLK, 256>>>();
    scan2_k<<<1, 256>>>();
    scan3_k<<<NBLK, 256>>>();
    fill_k<<<(N_EDGES + 255) / 256, 256>>>(ei);

    // ---- all weight packing in one launch ----
    conv_all_k<<<64, 256>>>(W_in, W_nbr, W_self);

    // ---- input projection: hpkA = pack(x @ W_in + b_in) ----
    gemm_in_k<<<gemm_blocks, 256>>>(x, w2, b_in, hpkA, M);

    const uint2* hcur = hpkA;
    for (int l = 0; l < NUM_LAYERS; l++) {
        const float* bs = b_self + (size_t)l * HIDDEN;
        const uint2* wn = w2 + 2048 + l * 4096;
        const uint2* ws = w2 + 2048 + (3 + l) * 4096;
        uint2* hnext = (hcur == hpkA) ? hpkB : hpkA;

        // one launch computes both: t16 = h@Wn (fp16), z = h@Ws + b (fp32)
        dim3 grid(gemm_blocks, 2);
        gemm_layer_k<<<grid, 256>>>(hcur, wn, ws, bs, t16, z, M);
        // h' = elu(z + gather(t)/deg)
        if (l == NUM_LAYERS - 1)
            gather_fused_k<1><<<(N_NODES * 32 + 255) / 256, 256>>>(t16, z, out);
        else
            gather_fused_k<0><<<(N_NODES * 32 + 255) / 256, 256>>>(t16, z, hnext);

        hcur = hnext;
    }
}